// round 2
// baseline (speedup 1.0000x reference)
#include <cuda_runtime.h>
#include <math.h>

// Problem constants
#define HDIM 1024
#define NHEAD 16
#define HD 64
#define HH 32
#define LAT 256
#define IDIM 1024
#define NEXP 7
#define BB 4
#define SS 1024
#define TT 4096            // BB*SS tokens
#define HBUF_ROWS 8704     // padded routed rows (2*TT + 7*64, rounded up)

// ---------------- scratch (device globals; no allocation allowed) ----------------
__device__ float g_xn1[TT * HDIM];
__device__ float g_kvlat[TT * LAT];
__device__ float g_qlat[TT * LAT];
__device__ float g_khalf[TT * NHEAD * HH];
__device__ float g_qhalf[TT * NHEAD * HH];
__device__ float g_qropeb[TT * NHEAD * HH];
__device__ float g_kropeb[TT * NHEAD * HH];
__device__ float g_v[TT * HDIM];
__device__ float g_kk[TT * HDIM];
__device__ float g_qq[TT * HDIM];
__device__ float g_y[TT * HDIM];
__device__ float g_x1[TT * HDIM];
__device__ float g_xn2[TT * HDIM];
__device__ float g_hmids[TT * IDIM];
__device__ float g_sharedo[TT * HDIM];
__device__ float g_hbuf[HBUF_ROWS * IDIM];
__device__ float g_slot[TT * 2 * HDIM];
__device__ int   g_topidx[TT * 2];
__device__ float g_topwt[TT * 2];
__device__ int   g_cnt[NEXP];
__device__ int   g_poff[NEXP + 1];
__device__ int   g_fill[NEXP];
__device__ int   g_list[HBUF_ROWS];

// ---------------- rmsnorm: norm = sqrt(mean(x^2)) + eps; y = x/norm * w ----------
__global__ void rmsnorm_kernel(const float* __restrict__ x,
                               const float* __restrict__ w,
                               float* __restrict__ out) {
    int t = blockIdx.x;
    const float* xr = x + (size_t)t * HDIM;
    float ss = 0.f;
    for (int h = threadIdx.x; h < HDIM; h += blockDim.x) {
        float v = xr[h];
        ss += v * v;
    }
    __shared__ float red[32];
    #pragma unroll
    for (int o = 16; o; o >>= 1) ss += __shfl_xor_sync(0xffffffffu, ss, o);
    if ((threadIdx.x & 31) == 0) red[threadIdx.x >> 5] = ss;
    __syncthreads();
    if (threadIdx.x < 32) {
        float v = (threadIdx.x < (blockDim.x >> 5)) ? red[threadIdx.x] : 0.f;
        #pragma unroll
        for (int o = 16; o; o >>= 1) v += __shfl_xor_sync(0xffffffffu, v, o);
        if (threadIdx.x == 0) red[0] = v;
    }
    __syncthreads();
    float inv = 1.0f / (sqrtf(red[0] * (1.0f / HDIM)) + 1e-5f);
    float* orow = out + (size_t)t * HDIM;
    for (int h = threadIdx.x; h < HDIM; h += blockDim.x)
        orow[h] = xr[h] * inv * w[h];
}

// ---------------- tiled SGEMM: C = A[M,K] @ B[K,N] (+ Dres) --------------------
// BM=BN=64, BK=16, 256 threads, 4x4 per-thread micro-tile. All dims multiples of 64/16.
__global__ void __launch_bounds__(256) sgemm_kernel(
    const float* __restrict__ A, const float* __restrict__ Bm,
    const float* __restrict__ Dres, float* __restrict__ C,
    int M, int N, int K) {
    __shared__ float As[16 * 64];  // As[k][m]
    __shared__ float Bs[16 * 64];  // Bs[k][n]
    int tid = threadIdx.x;
    int tx = tid & 15, ty = tid >> 4;
    int m0 = blockIdx.y * 64, n0 = blockIdx.x * 64;
    int arow = tid >> 2, acol = (tid & 3) << 2;   // A loader: row 0..63, 4 cols
    int brow = tid >> 4, bcol = (tid & 15) << 2;  // B loader: row 0..15, 4 cols
    const float* aptr = A + (size_t)(m0 + arow) * K + acol;
    const float* bptr = Bm + (size_t)brow * N + n0 + bcol;
    float acc[4][4] = {};
    for (int k0 = 0; k0 < K; k0 += 16) {
        float4 av = *(const float4*)(aptr + k0);
        float4 bv = *(const float4*)(bptr + (size_t)k0 * N);
        As[(acol + 0) * 64 + arow] = av.x;
        As[(acol + 1) * 64 + arow] = av.y;
        As[(acol + 2) * 64 + arow] = av.z;
        As[(acol + 3) * 64 + arow] = av.w;
        *(float4*)&Bs[brow * 64 + bcol] = bv;
        __syncthreads();
        #pragma unroll
        for (int k = 0; k < 16; k++) {
            float4 a4 = *(const float4*)&As[k * 64 + ty * 4];
            float4 b4 = *(const float4*)&Bs[k * 64 + tx * 4];
            float a[4] = {a4.x, a4.y, a4.z, a4.w};
            float b[4] = {b4.x, b4.y, b4.z, b4.w};
            #pragma unroll
            for (int i = 0; i < 4; i++)
                #pragma unroll
                for (int j = 0; j < 4; j++)
                    acc[i][j] = fmaf(a[i], b[j], acc[i][j]);
        }
        __syncthreads();
    }
    #pragma unroll
    for (int i = 0; i < 4; i++) {
        int m = m0 + ty * 4 + i;
        float4 r = {acc[i][0], acc[i][1], acc[i][2], acc[i][3]};
        if (Dres) {
            float4 d = *(const float4*)(Dres + (size_t)m * N + n0 + tx * 4);
            r.x += d.x; r.y += d.y; r.z += d.z; r.w += d.w;
        }
        *(float4*)(C + (size_t)m * N + n0 + tx * 4) = r;
    }
}

__device__ __forceinline__ float silu_f(float g) {
    return g / (1.0f + __expf(-g));
}

// ---------------- dual GEMM with SiLU fuse: C = silu(A@B0) * (A@B1) -------------
__global__ void __launch_bounds__(256) sgemm_dual_silu_kernel(
    const float* __restrict__ A, const float* __restrict__ B0,
    const float* __restrict__ B1, float* __restrict__ C,
    int M, int N, int K) {
    __shared__ float As[16 * 64];
    __shared__ float Bs0[16 * 64];
    __shared__ float Bs1[16 * 64];
    int tid = threadIdx.x;
    int tx = tid & 15, ty = tid >> 4;
    int m0 = blockIdx.y * 64, n0 = blockIdx.x * 64;
    int arow = tid >> 2, acol = (tid & 3) << 2;
    int brow = tid >> 4, bcol = (tid & 15) << 2;
    const float* aptr = A + (size_t)(m0 + arow) * K + acol;
    const float* b0p = B0 + (size_t)brow * N + n0 + bcol;
    const float* b1p = B1 + (size_t)brow * N + n0 + bcol;
    float accg[4][4] = {}, accu[4][4] = {};
    for (int k0 = 0; k0 < K; k0 += 16) {
        float4 av = *(const float4*)(aptr + k0);
        float4 b0v = *(const float4*)(b0p + (size_t)k0 * N);
        float4 b1v = *(const float4*)(b1p + (size_t)k0 * N);
        As[(acol + 0) * 64 + arow] = av.x;
        As[(acol + 1) * 64 + arow] = av.y;
        As[(acol + 2) * 64 + arow] = av.z;
        As[(acol + 3) * 64 + arow] = av.w;
        *(float4*)&Bs0[brow * 64 + bcol] = b0v;
        *(float4*)&Bs1[brow * 64 + bcol] = b1v;
        __syncthreads();
        #pragma unroll
        for (int k = 0; k < 16; k++) {
            float4 a4 = *(const float4*)&As[k * 64 + ty * 4];
            float4 g4 = *(const float4*)&Bs0[k * 64 + tx * 4];
            float4 u4 = *(const float4*)&Bs1[k * 64 + tx * 4];
            float a[4] = {a4.x, a4.y, a4.z, a4.w};
            float gb[4] = {g4.x, g4.y, g4.z, g4.w};
            float ub[4] = {u4.x, u4.y, u4.z, u4.w};
            #pragma unroll
            for (int i = 0; i < 4; i++)
                #pragma unroll
                for (int j = 0; j < 4; j++) {
                    accg[i][j] = fmaf(a[i], gb[j], accg[i][j]);
                    accu[i][j] = fmaf(a[i], ub[j], accu[i][j]);
                }
        }
        __syncthreads();
    }
    #pragma unroll
    for (int i = 0; i < 4; i++) {
        int m = m0 + ty * 4 + i;
        float4 r;
        r.x = silu_f(accg[i][0]) * accu[i][0];
        r.y = silu_f(accg[i][1]) * accu[i][1];
        r.z = silu_f(accg[i][2]) * accu[i][2];
        r.w = silu_f(accg[i][3]) * accu[i][3];
        *(float4*)(C + (size_t)m * N + n0 + tx * 4) = r;
    }
}

// ---------------- RoPE + concat into qq/kk [T, NH, 64] --------------------------
__global__ void rope_concat_kernel() {
    int i = blockIdx.x * blockDim.x + threadIdx.x;  // over TT*NHEAD*HH
    if (i >= TT * NHEAD * HH) return;
    int d = i & 31;
    int h = (i >> 5) & 15;
    int t = i >> 9;
    int s = t & (SS - 1);
    int j = d & 15;
    // inv_freq = 10000^{-(2j)/32}
    float invf = expf(-((float)j / 16.0f) * 9.210340371976184f);  // ln(10000)
    float ang = (float)s * invf;
    float c = cosf(ang), sn = sinf(ang);
    int o = t * HDIM + h * HD + d;
    float kr = g_kropeb[i];
    float krot = (d < 16) ? -g_kropeb[i + 16] : g_kropeb[i - 16];
    g_kk[o] = g_khalf[i];
    g_kk[o + HH] = kr * c + krot * sn;
    float qr = g_qropeb[i];
    float qrot = (d < 16) ? -g_qropeb[i + 16] : g_qropeb[i - 16];
    g_qq[o] = g_qhalf[i];
    g_qq[o + HH] = qr * c + qrot * sn;
}

// ---------------- flash attention: causal, 64x64 tiles, d=64 --------------------
__global__ void __launch_bounds__(256) flash_kernel() {
    extern __shared__ float sm[];
    float* Qst = sm;             // [d][q] 64x64, Q scaled by 1/8
    float* Kst = sm + 4096;      // [d][k] 64x64
    float* Vs  = sm + 8192;      // [k][d] 64x64
    float* Pst = sm + 12288;     // [k][q] 64x65 (padded)
    int qt = blockIdx.x, h = blockIdx.y, b = blockIdx.z;
    int tid = threadIdx.x;
    int tx = tid & 15, ty = tid >> 4;
    // load Q transposed, scaled
    {
        int r = tid >> 2;
        int c0 = (tid & 3) << 4;
        const float* src = g_qq + ((size_t)(b * SS + qt * 64 + r)) * HDIM + h * HD + c0;
        #pragma unroll
        for (int u = 0; u < 4; u++) {
            float4 v4 = *(const float4*)(src + u * 4);
            Qst[(c0 + u * 4 + 0) * 64 + r] = v4.x * 0.125f;
            Qst[(c0 + u * 4 + 1) * 64 + r] = v4.y * 0.125f;
            Qst[(c0 + u * 4 + 2) * 64 + r] = v4.z * 0.125f;
            Qst[(c0 + u * 4 + 3) * 64 + r] = v4.w * 0.125f;
        }
    }
    float o[4][4] = {};
    float m_i[4], l_i[4];
    #pragma unroll
    for (int i = 0; i < 4; i++) { m_i[i] = -3.4e38f; l_i[i] = 0.f; }

    for (int kt = 0; kt <= qt; kt++) {
        __syncthreads();  // protect Kst/Vs/Pst from previous iter readers; also Q store
        {
            int r = tid >> 2;
            int c0 = (tid & 3) << 4;
            const float* ks = g_kk + ((size_t)(b * SS + kt * 64 + r)) * HDIM + h * HD + c0;
            const float* vs = g_v + ((size_t)(b * SS + kt * 64 + r)) * HDIM + h * HD + c0;
            #pragma unroll
            for (int u = 0; u < 4; u++) {
                float4 v4 = *(const float4*)(ks + u * 4);
                Kst[(c0 + u * 4 + 0) * 64 + r] = v4.x;
                Kst[(c0 + u * 4 + 1) * 64 + r] = v4.y;
                Kst[(c0 + u * 4 + 2) * 64 + r] = v4.z;
                Kst[(c0 + u * 4 + 3) * 64 + r] = v4.w;
                *(float4*)&Vs[r * 64 + c0 + u * 4] = *(const float4*)(vs + u * 4);
            }
        }
        __syncthreads();
        // S = Q K^T (Q pre-scaled)
        float s[4][4] = {};
        #pragma unroll 4
        for (int d = 0; d < 64; d++) {
            float4 a4 = *(const float4*)&Qst[d * 64 + ty * 4];
            float4 b4 = *(const float4*)&Kst[d * 64 + tx * 4];
            float a[4] = {a4.x, a4.y, a4.z, a4.w};
            float bb[4] = {b4.x, b4.y, b4.z, b4.w};
            #pragma unroll
            for (int i = 0; i < 4; i++)
                #pragma unroll
                for (int j = 0; j < 4; j++)
                    s[i][j] = fmaf(a[i], bb[j], s[i][j]);
        }
        if (kt == qt) {
            #pragma unroll
            for (int i = 0; i < 4; i++)
                #pragma unroll
                for (int j = 0; j < 4; j++)
                    if (tx * 4 + j > ty * 4 + i) s[i][j] = -3.4e38f;
        }
        // online softmax per row (rows shared across 16 lanes)
        #pragma unroll
        for (int i = 0; i < 4; i++) {
            float mx = fmaxf(fmaxf(s[i][0], s[i][1]), fmaxf(s[i][2], s[i][3]));
            #pragma unroll
            for (int off = 8; off; off >>= 1)
                mx = fmaxf(mx, __shfl_xor_sync(0xffffffffu, mx, off));
            float mnew = fmaxf(m_i[i], mx);
            float alpha = __expf(m_i[i] - mnew);
            float rsum = 0.f;
            #pragma unroll
            for (int j = 0; j < 4; j++) {
                float p = __expf(s[i][j] - mnew);
                s[i][j] = p;
                rsum += p;
            }
            #pragma unroll
            for (int off = 8; off; off >>= 1)
                rsum += __shfl_xor_sync(0xffffffffu, rsum, off);
            l_i[i] = l_i[i] * alpha + rsum;
            m_i[i] = mnew;
            #pragma unroll
            for (int j = 0; j < 4; j++) {
                o[i][j] *= alpha;
                Pst[(tx * 4 + j) * 65 + ty * 4 + i] = s[i][j];
            }
        }
        __syncthreads();
        // O += P @ V
        #pragma unroll 4
        for (int k = 0; k < 64; k++) {
            float a[4];
            #pragma unroll
            for (int i = 0; i < 4; i++) a[i] = Pst[k * 65 + ty * 4 + i];
            float4 b4 = *(const float4*)&Vs[k * 64 + tx * 4];
            float bb[4] = {b4.x, b4.y, b4.z, b4.w};
            #pragma unroll
            for (int i = 0; i < 4; i++)
                #pragma unroll
                for (int j = 0; j < 4; j++)
                    o[i][j] = fmaf(a[i], bb[j], o[i][j]);
        }
    }
    #pragma unroll
    for (int i = 0; i < 4; i++) {
        float inv = 1.0f / l_i[i];
        int q = qt * 64 + ty * 4 + i;
        float4 r = {o[i][0] * inv, o[i][1] * inv, o[i][2] * inv, o[i][3] * inv};
        *(float4*)(g_y + ((size_t)(b * SS + q)) * HDIM + h * HD + tx * 4) = r;
    }
}

// ---------------- router: logits -> sigmoid -> top2 -> normalized weights -------
__global__ void zero_cnt_kernel() {
    if (threadIdx.x < NEXP) g_cnt[threadIdx.x] = 0;
}

__global__ void router_kernel(const float* __restrict__ Wr,
                              const float* __restrict__ bias) {
    int t = blockIdx.x * (blockDim.x >> 5) + (threadIdx.x >> 5);
    int lane = threadIdx.x & 31;
    if (t >= TT) return;
    const float* xr = g_xn2 + (size_t)t * HDIM;
    float acc[NEXP] = {};
    for (int h = lane; h < HDIM; h += 32) {
        float xv = xr[h];
        #pragma unroll
        for (int e = 0; e < NEXP; e++)
            acc[e] = fmaf(xv, Wr[h * NEXP + e], acc[e]);
    }
    #pragma unroll
    for (int e = 0; e < NEXP; e++)
        #pragma unroll
        for (int o = 16; o; o >>= 1)
            acc[e] += __shfl_xor_sync(0xffffffffu, acc[e], o);
    if (lane == 0) {
        float p[NEXP];
        #pragma unroll
        for (int e = 0; e < NEXP; e++)
            p[e] = 1.0f / (1.0f + expf(-(acc[e] + bias[e])));
        int i0 = 0;
        #pragma unroll
        for (int e = 1; e < NEXP; e++) if (p[e] > p[i0]) i0 = e;
        int i1 = (i0 == 0) ? 1 : 0;
        #pragma unroll
        for (int e = 0; e < NEXP; e++)
            if (e != i0 && p[e] > p[i1]) i1 = e;
        float ssum = p[i0] + p[i1];
        g_topidx[2 * t] = i0;
        g_topidx[2 * t + 1] = i1;
        g_topwt[2 * t] = p[i0] / ssum;
        g_topwt[2 * t + 1] = p[i1] / ssum;
        atomicAdd(&g_cnt[i0], 1);
        atomicAdd(&g_cnt[i1], 1);
    }
}

__global__ void prefix_kernel() {
    if (threadIdx.x == 0) {
        int off = 0;
        for (int e = 0; e < NEXP; e++) {
            g_poff[e] = off;
            off += (g_cnt[e] + 63) & ~63;
            g_fill[e] = 0;
        }
        g_poff[NEXP] = off;
    }
}

__global__ void scatter_kernel() {
    int t = blockIdx.x * blockDim.x + threadIdx.x;
    if (t >= TT) return;
    #pragma unroll
    for (int s = 0; s < 2; s++) {
        int e = g_topidx[2 * t + s];
        int pos = atomicAdd(&g_fill[e], 1);
        g_list[g_poff[e] + pos] = 2 * t + s;
    }
}

// ---------------- routed expert up: hbuf = silu(gx@Wg_e)*(gx@Wu_e) --------------
__global__ void __launch_bounds__(256) routed_up_kernel(
    const float* __restrict__ Wg, const float* __restrict__ Wu) {
    __shared__ float As[16 * 64];
    __shared__ float Bs0[16 * 64];
    __shared__ float Bs1[16 * 64];
    __shared__ int spoff[NEXP + 1];
    __shared__ int scnt[NEXP];
    int tid = threadIdx.x;
    if (tid <= NEXP) spoff[tid] = g_poff[tid];
    if (tid < NEXP) scnt[tid] = g_cnt[tid];
    __syncthreads();
    int m0 = blockIdx.y * 64;
    if (m0 >= spoff[NEXP]) return;
    int e = 0;
    while (m0 >= spoff[e + 1]) e++;
    int n0 = blockIdx.x * 64;
    int tx = tid & 15, ty = tid >> 4;
    int arow = tid >> 2, acol = (tid & 3) << 2;
    int brow = tid >> 4, bcol = (tid & 15) << 2;
    int grow = m0 + arow;
    int aloc = grow - spoff[e];
    int tok = (aloc < scnt[e]) ? (g_list[grow] >> 1) : 0;
    const float* aptr = g_xn2 + (size_t)tok * HDIM + acol;
    const float* b0p = Wg + (size_t)e * HDIM * IDIM + (size_t)brow * IDIM + n0 + bcol;
    const float* b1p = Wu + (size_t)e * HDIM * IDIM + (size_t)brow * IDIM + n0 + bcol;
    float accg[4][4] = {}, accu[4][4] = {};
    for (int k0 = 0; k0 < HDIM; k0 += 16) {
        float4 av = *(const float4*)(aptr + k0);
        float4 b0v = *(const float4*)(b0p + (size_t)k0 * IDIM);
        float4 b1v = *(const float4*)(b1p + (size_t)k0 * IDIM);
        As[(acol + 0) * 64 + arow] = av.x;
        As[(acol + 1) * 64 + arow] = av.y;
        As[(acol + 2) * 64 + arow] = av.z;
        As[(acol + 3) * 64 + arow] = av.w;
        *(float4*)&Bs0[brow * 64 + bcol] = b0v;
        *(float4*)&Bs1[brow * 64 + bcol] = b1v;
        __syncthreads();
        #pragma unroll
        for (int k = 0; k < 16; k++) {
            float4 a4 = *(const float4*)&As[k * 64 + ty * 4];
            float4 g4 = *(const float4*)&Bs0[k * 64 + tx * 4];
            float4 u4 = *(const float4*)&Bs1[k * 64 + tx * 4];
            float a[4] = {a4.x, a4.y, a4.z, a4.w};
            float gb[4] = {g4.x, g4.y, g4.z, g4.w};
            float ub[4] = {u4.x, u4.y, u4.z, u4.w};
            #pragma unroll
            for (int i = 0; i < 4; i++)
                #pragma unroll
                for (int j = 0; j < 4; j++) {
                    accg[i][j] = fmaf(a[i], gb[j], accg[i][j]);
                    accu[i][j] = fmaf(a[i], ub[j], accu[i][j]);
                }
        }
        __syncthreads();
    }
    #pragma unroll
    for (int i = 0; i < 4; i++) {
        int m = m0 + ty * 4 + i;
        if ((m - spoff[e]) < scnt[e]) {
            float4 r;
            r.x = silu_f(accg[i][0]) * accu[i][0];
            r.y = silu_f(accg[i][1]) * accu[i][1];
            r.z = silu_f(accg[i][2]) * accu[i][2];
            r.w = silu_f(accg[i][3]) * accu[i][3];
            *(float4*)(g_hbuf + (size_t)m * IDIM + n0 + tx * 4) = r;
        }
    }
}

// ---------------- routed expert down: slotbuf[token,slot] = hbuf @ Wd_e ---------
__global__ void __launch_bounds__(256) routed_down_kernel(
    const float* __restrict__ Wd) {
    __shared__ float As[16 * 64];
    __shared__ float Bs[16 * 64];
    __shared__ int spoff[NEXP + 1];
    __shared__ int scnt[NEXP];
    int tid = threadIdx.x;
    if (tid <= NEXP) spoff[tid] = g_poff[tid];
    if (tid < NEXP) scnt[tid] = g_cnt[tid];
    __syncthreads();
    int m0 = blockIdx.y * 64;
    if (m0 >= spoff[NEXP]) return;
    int e = 0;
    while (m0 >= spoff[e + 1]) e++;
    int n0 = blockIdx.x * 64;
    int tx = tid & 15, ty = tid >> 4;
    int arow = tid >> 2, acol = (tid & 3) << 2;
    int brow = tid >> 4, bcol = (tid & 15) << 2;
    const float* aptr = g_hbuf + (size_t)(m0 + arow) * IDIM + acol;
    const float* bptr = Wd + (size_t)e * IDIM * HDIM + (size_t)brow * HDIM + n0 + bcol;
    float acc[4][4] = {};
    for (int k0 = 0; k0 < IDIM; k0 += 16) {
        float4 av = *(const float4*)(aptr + k0);
        float4 bv = *(const float4*)(bptr + (size_t)k0 * HDIM);
        As[(acol + 0) * 64 + arow] = av.x;
        As[(acol + 1) * 64 + arow] = av.y;
        As[(acol + 2) * 64 + arow] = av.z;
        As[(acol + 3) * 64 + arow] = av.w;
        *(float4*)&Bs[brow * 64 + bcol] = bv;
        __syncthreads();
        #pragma unroll
        for (int k = 0; k < 16; k++) {
            float4 a4 = *(const float4*)&As[k * 64 + ty * 4];
            float4 b4 = *(const float4*)&Bs[k * 64 + tx * 4];
            float a[4] = {a4.x, a4.y, a4.z, a4.w};
            float b[4] = {b4.x, b4.y, b4.z, b4.w};
            #pragma unroll
            for (int i = 0; i < 4; i++)
                #pragma unroll
                for (int j = 0; j < 4; j++)
                    acc[i][j] = fmaf(a[i], b[j], acc[i][j]);
        }
        __syncthreads();
    }
    #pragma unroll
    for (int i = 0; i < 4; i++) {
        int m = m0 + ty * 4 + i;
        if ((m - spoff[e]) < scnt[e]) {
            int enc = g_list[m];  // 2*token + slot
            float4 r = {acc[i][0], acc[i][1], acc[i][2], acc[i][3]};
            *(float4*)(g_slot + (size_t)enc * HDIM + n0 + tx * 4) = r;
        }
    }
}

// ---------------- final combine: out = x1 + shared + w0*slot0 + w1*slot1 --------
__global__ void combine_kernel(float* __restrict__ out) {
    int i = blockIdx.x * blockDim.x + threadIdx.x;  // over TT*HDIM/4
    if (i >= TT * HDIM / 4) return;
    int c = i & (HDIM / 4 - 1);
    int t = i / (HDIM / 4);
    float w0 = g_topwt[2 * t], w1 = g_topwt[2 * t + 1];
    float4 a = ((const float4*)g_x1)[i];
    float4 sh = ((const float4*)g_sharedo)[i];
    float4 s0 = ((const float4*)g_slot)[(size_t)(2 * t) * (HDIM / 4) + c];
    float4 s1 = ((const float4*)g_slot)[(size_t)(2 * t + 1) * (HDIM / 4) + c];
    float4 r;
    r.x = a.x + sh.x + w0 * s0.x + w1 * s1.x;
    r.y = a.y + sh.y + w0 * s0.y + w1 * s1.y;
    r.z = a.z + sh.z + w0 * s0.z + w1 * s1.z;
    r.w = a.w + sh.w + w0 * s0.w + w1 * s1.w;
    ((float4*)out)[i] = r;
}

// ================================ host launcher =================================
static float* sym_f(const void* s) {
    void* p = nullptr;
    cudaGetSymbolAddress(&p, s);
    return (float*)p;
}

extern "C" void kernel_launch(void* const* d_in, const int* in_sizes, int n_in,
                              void* d_out, int out_size) {
    const float* x        = (const float*)d_in[0];
    const float* w_ln1    = (const float*)d_in[1];
    const float* w_ln2    = (const float*)d_in[2];
    const float* W_kvd    = (const float*)d_in[3];
    const float* W_qd     = (const float*)d_in[4];
    const float* W_ku     = (const float*)d_in[5];
    const float* W_qu     = (const float*)d_in[6];
    const float* W_vu     = (const float*)d_in[7];
    const float* W_ropeq  = (const float*)d_in[8];
    const float* W_ropek  = (const float*)d_in[9];
    const float* W_o      = (const float*)d_in[10];
    const float* Wg_s     = (const float*)d_in[11];
    const float* Wu_s     = (const float*)d_in[12];
    const float* Wd_s     = (const float*)d_in[13];
    const float* Wg_r     = (const float*)d_in[14];
    const float* Wu_r     = (const float*)d_in[15];
    const float* Wd_r     = (const float*)d_in[16];
    const float* W_router = (const float*)d_in[17];
    const float* r_bias   = (const float*)d_in[18];
    float* out = (float*)d_out;

    float* xn1    = sym_f(g_xn1);
    float* kvlat  = sym_f(g_kvlat);
    float* qlat   = sym_f(g_qlat);
    float* khalf  = sym_f(g_khalf);
    float* qhalf  = sym_f(g_qhalf);
    float* qropeb = sym_f(g_qropeb);
    float* kropeb = sym_f(g_kropeb);
    float* vbuf   = sym_f(g_v);
    float* ybuf   = sym_f(g_y);
    float* x1     = sym_f(g_x1);
    float* xn2    = sym_f(g_xn2);
    float* hmids  = sym_f(g_hmids);
    float* sharedo = sym_f(g_sharedo);

    // flash kernel needs >48KB dynamic smem
    static const int FLASH_SMEM = (4096 * 3 + 64 * 65) * 4;  // 65792 B
    cudaFuncSetAttribute(flash_kernel, cudaFuncAttributeMaxDynamicSharedMemorySize,
                         FLASH_SMEM);

    // ---- MLA ----
    rmsnorm_kernel<<<TT, 256>>>(x, w_ln1, xn1);
    sgemm_kernel<<<dim3(LAT / 64, TT / 64), 256>>>(xn1, W_kvd, nullptr, kvlat, TT, LAT, HDIM);
    sgemm_kernel<<<dim3(LAT / 64, TT / 64), 256>>>(xn1, W_qd, nullptr, qlat, TT, LAT, HDIM);
    sgemm_kernel<<<dim3(512 / 64, TT / 64), 256>>>(kvlat, W_ku, nullptr, khalf, TT, 512, LAT);
    sgemm_kernel<<<dim3(512 / 64, TT / 64), 256>>>(qlat, W_qu, nullptr, qhalf, TT, 512, LAT);
    sgemm_kernel<<<dim3(HDIM / 64, TT / 64), 256>>>(kvlat, W_vu, nullptr, vbuf, TT, HDIM, LAT);
    sgemm_kernel<<<dim3(512 / 64, TT / 64), 256>>>(qlat, W_ropeq, nullptr, qropeb, TT, 512, LAT);
    sgemm_kernel<<<dim3(512 / 64, TT / 64), 256>>>(xn1, W_ropek, nullptr, kropeb, TT, 512, HDIM);
    {
        int n = TT * NHEAD * HH;
        rope_concat_kernel<<<(n + 255) / 256, 256>>>();
    }
    flash_kernel<<<dim3(SS / 64, NHEAD, BB), 256, FLASH_SMEM>>>();
    // x1 = x + y @ W_o
    sgemm_kernel<<<dim3(HDIM / 64, TT / 64), 256>>>(ybuf, W_o, x, x1, TT, HDIM, HDIM);

    // ---- MoE ----
    rmsnorm_kernel<<<TT, 256>>>(x1, w_ln2, xn2);
    zero_cnt_kernel<<<1, 32>>>();
    router_kernel<<<TT / 4, 128>>>(W_router, r_bias);
    prefix_kernel<<<1, 32>>>();
    scatter_kernel<<<(TT + 255) / 256, 256>>>();
    // shared expert
    sgemm_dual_silu_kernel<<<dim3(IDIM / 64, TT / 64), 256>>>(xn2, Wg_s, Wu_s, hmids,
                                                              TT, IDIM, HDIM);
    sgemm_kernel<<<dim3(HDIM / 64, TT / 64), 256>>>(hmids, Wd_s, nullptr, sharedo,
                                                    TT, HDIM, IDIM);
    // routed experts (sparse, padded segments)
    routed_up_kernel<<<dim3(IDIM / 64, HBUF_ROWS / 64), 256>>>(Wg_r, Wu_r);
    routed_down_kernel<<<dim3(HDIM / 64, HBUF_ROWS / 64), 256>>>(Wd_r);
    // out = x1 + shared + weighted routed
    combine_kernel<<<(TT * HDIM / 4 + 255) / 256, 256>>>(out);
}

// round 3
// speedup vs baseline: 1.1131x; 1.1131x over previous
#include <cuda_runtime.h>
#include <math.h>

// Problem constants
#define HDIM 1024
#define NHEAD 16
#define HD 64
#define HH 32
#define LAT 256
#define IDIM 1024
#define NEXP 7
#define BB 4
#define SS 1024
#define TT 4096            // BB*SS tokens
#define HBUF_ROWS 9216     // padded routed rows (2*TT + 7*127, rounded to 128)

// ---------------- scratch (device globals; no allocation allowed) ----------------
__device__ float g_xn1[TT * HDIM];
__device__ float g_kvlat[TT * LAT];
__device__ float g_qlat[TT * LAT];
__device__ float g_khalf[TT * NHEAD * HH];
__device__ float g_qhalf[TT * NHEAD * HH];
__device__ float g_qropeb[TT * NHEAD * HH];
__device__ float g_kropeb[TT * NHEAD * HH];
__device__ float g_v[TT * HDIM];
__device__ float g_kk[TT * HDIM];
__device__ float g_qq[TT * HDIM];
__device__ float g_y[TT * HDIM];
__device__ float g_x1[TT * HDIM];
__device__ float g_xn2[TT * HDIM];
__device__ float g_hmids[TT * IDIM];
__device__ float g_sharedo[TT * HDIM];
__device__ float g_hbuf[HBUF_ROWS * IDIM];
__device__ float g_slot[TT * 2 * HDIM];
__device__ int   g_topidx[TT * 2];
__device__ float g_topwt[TT * 2];
__device__ int   g_cnt[NEXP];
__device__ int   g_poff[NEXP + 1];
__device__ int   g_fill[NEXP];
__device__ int   g_list[HBUF_ROWS];

__device__ __forceinline__ float silu_f(float g) {
    return g / (1.0f + __expf(-g));
}

// ---------------- rmsnorm: norm = sqrt(mean(x^2)) + eps; y = x/norm * w ----------
__global__ void rmsnorm_kernel(const float* __restrict__ x,
                               const float* __restrict__ w,
                               float* __restrict__ out) {
    int t = blockIdx.x;
    const float* xr = x + (size_t)t * HDIM;
    float ss = 0.f;
    for (int h = threadIdx.x; h < HDIM; h += blockDim.x) {
        float v = xr[h];
        ss += v * v;
    }
    __shared__ float red[32];
    #pragma unroll
    for (int o = 16; o; o >>= 1) ss += __shfl_xor_sync(0xffffffffu, ss, o);
    if ((threadIdx.x & 31) == 0) red[threadIdx.x >> 5] = ss;
    __syncthreads();
    if (threadIdx.x < 32) {
        float v = (threadIdx.x < (blockDim.x >> 5)) ? red[threadIdx.x] : 0.f;
        #pragma unroll
        for (int o = 16; o; o >>= 1) v += __shfl_xor_sync(0xffffffffu, v, o);
        if (threadIdx.x == 0) red[0] = v;
    }
    __syncthreads();
    float inv = 1.0f / (sqrtf(red[0] * (1.0f / HDIM)) + 1e-5f);
    float* orow = out + (size_t)t * HDIM;
    for (int h = threadIdx.x; h < HDIM; h += blockDim.x)
        orow[h] = xr[h] * inv * w[h];
}

// =============== 128x128 SGEMM, 8x8 micro-tile, double-buffered ==================
// C = A[M,K] @ B[K,N] (+ Dres). M%128==0, N%128==0, K%16==0.
__global__ void __launch_bounds__(256) sgemm128_kernel(
    const float* __restrict__ A, const float* __restrict__ Bm,
    const float* __restrict__ Dres, float* __restrict__ C,
    int M, int N, int K) {
    __shared__ float As[2][16 * 132];  // [k][m], padded
    __shared__ float Bs[2][16 * 128];  // [k][n]
    int tid = threadIdx.x;
    int tx = tid & 15, ty = tid >> 4;
    int m0 = blockIdx.y * 128, n0 = blockIdx.x * 128;
    int arow = tid >> 1, acol = (tid & 1) * 8;   // A: 128 rows x 16 k-cols
    int brow = tid >> 4, bcol = (tid & 15) * 4;  // B: 16 k-rows x 128 n-cols
    const float* aptr = A + (size_t)(m0 + arow) * K + acol;
    const float* bptr = Bm + (size_t)brow * N + n0;
    float4 ra0 = *(const float4*)(aptr);
    float4 ra1 = *(const float4*)(aptr + 4);
    float4 rb0 = *(const float4*)(bptr + bcol);
    float4 rb1 = *(const float4*)(bptr + 64 + bcol);
    float acc[8][8] = {};
    int buf = 0;
    for (int k0 = 0; k0 < K; k0 += 16) {
        float* Asb = As[buf];
        float* Bsb = Bs[buf];
        Asb[(acol + 0) * 132 + arow] = ra0.x;
        Asb[(acol + 1) * 132 + arow] = ra0.y;
        Asb[(acol + 2) * 132 + arow] = ra0.z;
        Asb[(acol + 3) * 132 + arow] = ra0.w;
        Asb[(acol + 4) * 132 + arow] = ra1.x;
        Asb[(acol + 5) * 132 + arow] = ra1.y;
        Asb[(acol + 6) * 132 + arow] = ra1.z;
        Asb[(acol + 7) * 132 + arow] = ra1.w;
        *(float4*)&Bsb[brow * 128 + bcol] = rb0;
        *(float4*)&Bsb[brow * 128 + 64 + bcol] = rb1;
        __syncthreads();
        if (k0 + 16 < K) {
            ra0 = *(const float4*)(aptr + k0 + 16);
            ra1 = *(const float4*)(aptr + k0 + 20);
            rb0 = *(const float4*)(bptr + (size_t)(k0 + 16) * N + bcol);
            rb1 = *(const float4*)(bptr + (size_t)(k0 + 16) * N + 64 + bcol);
        }
        #pragma unroll
        for (int k = 0; k < 16; k++) {
            float4 a0 = *(const float4*)&Asb[k * 132 + ty * 4];
            float4 a1 = *(const float4*)&Asb[k * 132 + 64 + ty * 4];
            float4 b0 = *(const float4*)&Bsb[k * 128 + tx * 4];
            float4 b1 = *(const float4*)&Bsb[k * 128 + 64 + tx * 4];
            float a[8] = {a0.x, a0.y, a0.z, a0.w, a1.x, a1.y, a1.z, a1.w};
            float b[8] = {b0.x, b0.y, b0.z, b0.w, b1.x, b1.y, b1.z, b1.w};
            #pragma unroll
            for (int i = 0; i < 8; i++)
                #pragma unroll
                for (int j = 0; j < 8; j++)
                    acc[i][j] = fmaf(a[i], b[j], acc[i][j]);
        }
        buf ^= 1;
    }
    #pragma unroll
    for (int ii = 0; ii < 2; ii++) {
        #pragma unroll
        for (int i = 0; i < 4; i++) {
            int ai = ii * 4 + i;
            int m = m0 + ii * 64 + ty * 4 + i;
            float* crow = C + (size_t)m * N + n0;
            float4 r0 = {acc[ai][0], acc[ai][1], acc[ai][2], acc[ai][3]};
            float4 r1 = {acc[ai][4], acc[ai][5], acc[ai][6], acc[ai][7]};
            if (Dres) {
                const float* drow = Dres + (size_t)m * N + n0;
                float4 d0 = *(const float4*)(drow + tx * 4);
                float4 d1 = *(const float4*)(drow + 64 + tx * 4);
                r0.x += d0.x; r0.y += d0.y; r0.z += d0.z; r0.w += d0.w;
                r1.x += d1.x; r1.y += d1.y; r1.z += d1.z; r1.w += d1.w;
            }
            *(float4*)(crow + tx * 4) = r0;
            *(float4*)(crow + 64 + tx * 4) = r1;
        }
    }
}

// =============== 128x64 dual GEMM + SiLU: C = silu(A@B0)*(A@B1) ==================
__global__ void __launch_bounds__(256) dual128_kernel(
    const float* __restrict__ A, const float* __restrict__ B0,
    const float* __restrict__ B1, float* __restrict__ C,
    int M, int N, int K) {
    __shared__ float As[2][16 * 132];
    __shared__ float Bs0[2][16 * 64];
    __shared__ float Bs1[2][16 * 64];
    int tid = threadIdx.x;
    int tx = tid & 15, ty = tid >> 4;
    int m0 = blockIdx.y * 128, n0 = blockIdx.x * 64;
    int arow = tid >> 1, acol = (tid & 1) * 8;
    int brow = tid >> 4, bcol = (tid & 15) * 4;
    const float* aptr = A + (size_t)(m0 + arow) * K + acol;
    const float* b0p = B0 + (size_t)brow * N + n0 + bcol;
    const float* b1p = B1 + (size_t)brow * N + n0 + bcol;
    float4 ra0 = *(const float4*)(aptr);
    float4 ra1 = *(const float4*)(aptr + 4);
    float4 rb0 = *(const float4*)(b0p);
    float4 rb1 = *(const float4*)(b1p);
    float accg[8][4] = {}, accu[8][4] = {};
    int buf = 0;
    for (int k0 = 0; k0 < K; k0 += 16) {
        float* Asb = As[buf];
        float* B0b = Bs0[buf];
        float* B1b = Bs1[buf];
        Asb[(acol + 0) * 132 + arow] = ra0.x;
        Asb[(acol + 1) * 132 + arow] = ra0.y;
        Asb[(acol + 2) * 132 + arow] = ra0.z;
        Asb[(acol + 3) * 132 + arow] = ra0.w;
        Asb[(acol + 4) * 132 + arow] = ra1.x;
        Asb[(acol + 5) * 132 + arow] = ra1.y;
        Asb[(acol + 6) * 132 + arow] = ra1.z;
        Asb[(acol + 7) * 132 + arow] = ra1.w;
        *(float4*)&B0b[brow * 64 + bcol] = rb0;
        *(float4*)&B1b[brow * 64 + bcol] = rb1;
        __syncthreads();
        if (k0 + 16 < K) {
            ra0 = *(const float4*)(aptr + k0 + 16);
            ra1 = *(const float4*)(aptr + k0 + 20);
            rb0 = *(const float4*)(b0p + (size_t)(k0 + 16) * N);
            rb1 = *(const float4*)(b1p + (size_t)(k0 + 16) * N);
        }
        #pragma unroll
        for (int k = 0; k < 16; k++) {
            float4 a0 = *(const float4*)&Asb[k * 132 + ty * 4];
            float4 a1 = *(const float4*)&Asb[k * 132 + 64 + ty * 4];
            float4 g4 = *(const float4*)&B0b[k * 64 + tx * 4];
            float4 u4 = *(const float4*)&B1b[k * 64 + tx * 4];
            float a[8] = {a0.x, a0.y, a0.z, a0.w, a1.x, a1.y, a1.z, a1.w};
            float gb[4] = {g4.x, g4.y, g4.z, g4.w};
            float ub[4] = {u4.x, u4.y, u4.z, u4.w};
            #pragma unroll
            for (int i = 0; i < 8; i++)
                #pragma unroll
                for (int j = 0; j < 4; j++) {
                    accg[i][j] = fmaf(a[i], gb[j], accg[i][j]);
                    accu[i][j] = fmaf(a[i], ub[j], accu[i][j]);
                }
        }
        buf ^= 1;
    }
    #pragma unroll
    for (int ii = 0; ii < 2; ii++) {
        #pragma unroll
        for (int i = 0; i < 4; i++) {
            int ai = ii * 4 + i;
            int m = m0 + ii * 64 + ty * 4 + i;
            float4 r;
            r.x = silu_f(accg[ai][0]) * accu[ai][0];
            r.y = silu_f(accg[ai][1]) * accu[ai][1];
            r.z = silu_f(accg[ai][2]) * accu[ai][2];
            r.w = silu_f(accg[ai][3]) * accu[ai][3];
            *(float4*)(C + (size_t)m * N + n0 + tx * 4) = r;
        }
    }
}

// ---------------- RoPE + concat into qq/kk [T, NH, 64] --------------------------
__global__ void rope_concat_kernel() {
    int i = blockIdx.x * blockDim.x + threadIdx.x;  // over TT*NHEAD*HH
    if (i >= TT * NHEAD * HH) return;
    int d = i & 31;
    int h = (i >> 5) & 15;
    int t = i >> 9;
    int s = t & (SS - 1);
    int j = d & 15;
    float invf = expf(-((float)j / 16.0f) * 9.210340371976184f);  // ln(10000)
    float ang = (float)s * invf;
    float c = cosf(ang), sn = sinf(ang);
    int o = t * HDIM + h * HD + d;
    float kr = g_kropeb[i];
    float krot = (d < 16) ? -g_kropeb[i + 16] : g_kropeb[i - 16];
    g_kk[o] = g_khalf[i];
    g_kk[o + HH] = kr * c + krot * sn;
    float qr = g_qropeb[i];
    float qrot = (d < 16) ? -g_qropeb[i + 16] : g_qropeb[i - 16];
    g_qq[o] = g_qhalf[i];
    g_qq[o + HH] = qr * c + qrot * sn;
}

// ---------------- flash attention: causal, 64x64 tiles, d=64 --------------------
__global__ void __launch_bounds__(256) flash_kernel() {
    extern __shared__ float sm[];
    float* Qst = sm;             // [d][q] 64x64, Q scaled by 1/8
    float* Kst = sm + 4096;      // [d][k] 64x64
    float* Vs  = sm + 8192;      // [k][d] 64x64
    float* Pst = sm + 12288;     // [k][q] 64x65 (padded)
    int qt = blockIdx.x, h = blockIdx.y, b = blockIdx.z;
    int tid = threadIdx.x;
    int tx = tid & 15, ty = tid >> 4;
    {
        int r = tid >> 2;
        int c0 = (tid & 3) << 4;
        const float* src = g_qq + ((size_t)(b * SS + qt * 64 + r)) * HDIM + h * HD + c0;
        #pragma unroll
        for (int u = 0; u < 4; u++) {
            float4 v4 = *(const float4*)(src + u * 4);
            Qst[(c0 + u * 4 + 0) * 64 + r] = v4.x * 0.125f;
            Qst[(c0 + u * 4 + 1) * 64 + r] = v4.y * 0.125f;
            Qst[(c0 + u * 4 + 2) * 64 + r] = v4.z * 0.125f;
            Qst[(c0 + u * 4 + 3) * 64 + r] = v4.w * 0.125f;
        }
    }
    float o[4][4] = {};
    float m_i[4], l_i[4];
    #pragma unroll
    for (int i = 0; i < 4; i++) { m_i[i] = -3.4e38f; l_i[i] = 0.f; }

    for (int kt = 0; kt <= qt; kt++) {
        __syncthreads();
        {
            int r = tid >> 2;
            int c0 = (tid & 3) << 4;
            const float* ks = g_kk + ((size_t)(b * SS + kt * 64 + r)) * HDIM + h * HD + c0;
            const float* vs = g_v + ((size_t)(b * SS + kt * 64 + r)) * HDIM + h * HD + c0;
            #pragma unroll
            for (int u = 0; u < 4; u++) {
                float4 v4 = *(const float4*)(ks + u * 4);
                Kst[(c0 + u * 4 + 0) * 64 + r] = v4.x;
                Kst[(c0 + u * 4 + 1) * 64 + r] = v4.y;
                Kst[(c0 + u * 4 + 2) * 64 + r] = v4.z;
                Kst[(c0 + u * 4 + 3) * 64 + r] = v4.w;
                *(float4*)&Vs[r * 64 + c0 + u * 4] = *(const float4*)(vs + u * 4);
            }
        }
        __syncthreads();
        float s[4][4] = {};
        #pragma unroll 4
        for (int d = 0; d < 64; d++) {
            float4 a4 = *(const float4*)&Qst[d * 64 + ty * 4];
            float4 b4 = *(const float4*)&Kst[d * 64 + tx * 4];
            float a[4] = {a4.x, a4.y, a4.z, a4.w};
            float bb[4] = {b4.x, b4.y, b4.z, b4.w};
            #pragma unroll
            for (int i = 0; i < 4; i++)
                #pragma unroll
                for (int j = 0; j < 4; j++)
                    s[i][j] = fmaf(a[i], bb[j], s[i][j]);
        }
        if (kt == qt) {
            #pragma unroll
            for (int i = 0; i < 4; i++)
                #pragma unroll
                for (int j = 0; j < 4; j++)
                    if (tx * 4 + j > ty * 4 + i) s[i][j] = -3.4e38f;
        }
        #pragma unroll
        for (int i = 0; i < 4; i++) {
            float mx = fmaxf(fmaxf(s[i][0], s[i][1]), fmaxf(s[i][2], s[i][3]));
            #pragma unroll
            for (int off = 8; off; off >>= 1)
                mx = fmaxf(mx, __shfl_xor_sync(0xffffffffu, mx, off));
            float mnew = fmaxf(m_i[i], mx);
            float alpha = __expf(m_i[i] - mnew);
            float rsum = 0.f;
            #pragma unroll
            for (int j = 0; j < 4; j++) {
                float p = __expf(s[i][j] - mnew);
                s[i][j] = p;
                rsum += p;
            }
            #pragma unroll
            for (int off = 8; off; off >>= 1)
                rsum += __shfl_xor_sync(0xffffffffu, rsum, off);
            l_i[i] = l_i[i] * alpha + rsum;
            m_i[i] = mnew;
            #pragma unroll
            for (int j = 0; j < 4; j++) {
                o[i][j] *= alpha;
                Pst[(tx * 4 + j) * 65 + ty * 4 + i] = s[i][j];
            }
        }
        __syncthreads();
        #pragma unroll 4
        for (int k = 0; k < 64; k++) {
            float a[4];
            #pragma unroll
            for (int i = 0; i < 4; i++) a[i] = Pst[k * 65 + ty * 4 + i];
            float4 b4 = *(const float4*)&Vs[k * 64 + tx * 4];
            float bb[4] = {b4.x, b4.y, b4.z, b4.w};
            #pragma unroll
            for (int i = 0; i < 4; i++)
                #pragma unroll
                for (int j = 0; j < 4; j++)
                    o[i][j] = fmaf(a[i], bb[j], o[i][j]);
        }
    }
    #pragma unroll
    for (int i = 0; i < 4; i++) {
        float inv = 1.0f / l_i[i];
        int q = qt * 64 + ty * 4 + i;
        float4 r = {o[i][0] * inv, o[i][1] * inv, o[i][2] * inv, o[i][3] * inv};
        *(float4*)(g_y + ((size_t)(b * SS + q)) * HDIM + h * HD + tx * 4) = r;
    }
}

// ---------------- router ---------------------------------------------------------
__global__ void zero_cnt_kernel() {
    if (threadIdx.x < NEXP) g_cnt[threadIdx.x] = 0;
}

__global__ void router_kernel(const float* __restrict__ Wr,
                              const float* __restrict__ bias) {
    int t = blockIdx.x * (blockDim.x >> 5) + (threadIdx.x >> 5);
    int lane = threadIdx.x & 31;
    if (t >= TT) return;
    const float* xr = g_xn2 + (size_t)t * HDIM;
    float acc[NEXP] = {};
    for (int h = lane; h < HDIM; h += 32) {
        float xv = xr[h];
        #pragma unroll
        for (int e = 0; e < NEXP; e++)
            acc[e] = fmaf(xv, Wr[h * NEXP + e], acc[e]);
    }
    #pragma unroll
    for (int e = 0; e < NEXP; e++)
        #pragma unroll
        for (int o = 16; o; o >>= 1)
            acc[e] += __shfl_xor_sync(0xffffffffu, acc[e], o);
    if (lane == 0) {
        float p[NEXP];
        #pragma unroll
        for (int e = 0; e < NEXP; e++)
            p[e] = 1.0f / (1.0f + expf(-(acc[e] + bias[e])));
        int i0 = 0;
        #pragma unroll
        for (int e = 1; e < NEXP; e++) if (p[e] > p[i0]) i0 = e;
        int i1 = (i0 == 0) ? 1 : 0;
        #pragma unroll
        for (int e = 0; e < NEXP; e++)
            if (e != i0 && p[e] > p[i1]) i1 = e;
        float ssum = p[i0] + p[i1];
        g_topidx[2 * t] = i0;
        g_topidx[2 * t + 1] = i1;
        g_topwt[2 * t] = p[i0] / ssum;
        g_topwt[2 * t + 1] = p[i1] / ssum;
        atomicAdd(&g_cnt[i0], 1);
        atomicAdd(&g_cnt[i1], 1);
    }
}

__global__ void prefix_kernel() {
    if (threadIdx.x == 0) {
        int off = 0;
        for (int e = 0; e < NEXP; e++) {
            g_poff[e] = off;
            off += (g_cnt[e] + 127) & ~127;   // pad segments to 128 rows
            g_fill[e] = 0;
        }
        g_poff[NEXP] = off;
    }
}

__global__ void scatter_kernel() {
    int t = blockIdx.x * blockDim.x + threadIdx.x;
    if (t >= TT) return;
    #pragma unroll
    for (int s = 0; s < 2; s++) {
        int e = g_topidx[2 * t + s];
        int pos = atomicAdd(&g_fill[e], 1);
        g_list[g_poff[e] + pos] = 2 * t + s;
    }
}

// =============== routed expert up: hbuf = silu(gather(xn2)@Wg_e)*(...@Wu_e) ======
__global__ void __launch_bounds__(256) routed_up_kernel(
    const float* __restrict__ Wg, const float* __restrict__ Wu) {
    __shared__ float As[2][16 * 132];
    __shared__ float Bs0[2][16 * 64];
    __shared__ float Bs1[2][16 * 64];
    __shared__ int spoff[NEXP + 1];
    __shared__ int scnt[NEXP];
    int tid = threadIdx.x;
    if (tid <= NEXP) spoff[tid] = g_poff[tid];
    if (tid < NEXP) scnt[tid] = g_cnt[tid];
    __syncthreads();
    int m0 = blockIdx.y * 128;
    if (m0 >= spoff[NEXP]) return;
    int e = 0;
    while (m0 >= spoff[e + 1]) e++;
    int n0 = blockIdx.x * 64;
    int tx = tid & 15, ty = tid >> 4;
    int arow = tid >> 1, acol = (tid & 1) * 8;
    int brow = tid >> 4, bcol = (tid & 15) * 4;
    int grow = m0 + arow;
    int aloc = grow - spoff[e];
    int tok = (aloc < scnt[e]) ? (g_list[grow] >> 1) : 0;
    const float* aptr = g_xn2 + (size_t)tok * HDIM + acol;
    const float* b0p = Wg + (size_t)e * HDIM * IDIM + (size_t)brow * IDIM + n0 + bcol;
    const float* b1p = Wu + (size_t)e * HDIM * IDIM + (size_t)brow * IDIM + n0 + bcol;
    float4 ra0 = *(const float4*)(aptr);
    float4 ra1 = *(const float4*)(aptr + 4);
    float4 rb0 = *(const float4*)(b0p);
    float4 rb1 = *(const float4*)(b1p);
    float accg[8][4] = {}, accu[8][4] = {};
    int buf = 0;
    for (int k0 = 0; k0 < HDIM; k0 += 16) {
        float* Asb = As[buf];
        float* B0b = Bs0[buf];
        float* B1b = Bs1[buf];
        Asb[(acol + 0) * 132 + arow] = ra0.x;
        Asb[(acol + 1) * 132 + arow] = ra0.y;
        Asb[(acol + 2) * 132 + arow] = ra0.z;
        Asb[(acol + 3) * 132 + arow] = ra0.w;
        Asb[(acol + 4) * 132 + arow] = ra1.x;
        Asb[(acol + 5) * 132 + arow] = ra1.y;
        Asb[(acol + 6) * 132 + arow] = ra1.z;
        Asb[(acol + 7) * 132 + arow] = ra1.w;
        *(float4*)&B0b[brow * 64 + bcol] = rb0;
        *(float4*)&B1b[brow * 64 + bcol] = rb1;
        __syncthreads();
        if (k0 + 16 < HDIM) {
            ra0 = *(const float4*)(aptr + k0 + 16);
            ra1 = *(const float4*)(aptr + k0 + 20);
            rb0 = *(const float4*)(b0p + (size_t)(k0 + 16) * IDIM);
            rb1 = *(const float4*)(b1p + (size_t)(k0 + 16) * IDIM);
        }
        #pragma unroll
        for (int k = 0; k < 16; k++) {
            float4 a0 = *(const float4*)&Asb[k * 132 + ty * 4];
            float4 a1 = *(const float4*)&Asb[k * 132 + 64 + ty * 4];
            float4 g4 = *(const float4*)&B0b[k * 64 + tx * 4];
            float4 u4 = *(const float4*)&B1b[k * 64 + tx * 4];
            float a[8] = {a0.x, a0.y, a0.z, a0.w, a1.x, a1.y, a1.z, a1.w};
            float gb[4] = {g4.x, g4.y, g4.z, g4.w};
            float ub[4] = {u4.x, u4.y, u4.z, u4.w};
            #pragma unroll
            for (int i = 0; i < 8; i++)
                #pragma unroll
                for (int j = 0; j < 4; j++) {
                    accg[i][j] = fmaf(a[i], gb[j], accg[i][j]);
                    accu[i][j] = fmaf(a[i], ub[j], accu[i][j]);
                }
        }
        buf ^= 1;
    }
    #pragma unroll
    for (int ii = 0; ii < 2; ii++) {
        #pragma unroll
        for (int i = 0; i < 4; i++) {
            int ai = ii * 4 + i;
            int m = m0 + ii * 64 + ty * 4 + i;
            if ((m - spoff[e]) < scnt[e]) {
                float4 r;
                r.x = silu_f(accg[ai][0]) * accu[ai][0];
                r.y = silu_f(accg[ai][1]) * accu[ai][1];
                r.z = silu_f(accg[ai][2]) * accu[ai][2];
                r.w = silu_f(accg[ai][3]) * accu[ai][3];
                *(float4*)(g_hbuf + (size_t)m * IDIM + n0 + tx * 4) = r;
            }
        }
    }
}

// =============== routed expert down: slot[token,slot] = hbuf @ Wd_e ==============
__global__ void __launch_bounds__(256) routed_down_kernel(
    const float* __restrict__ Wd) {
    __shared__ float As[2][16 * 132];
    __shared__ float Bs[2][16 * 128];
    __shared__ int spoff[NEXP + 1];
    __shared__ int scnt[NEXP];
    int tid = threadIdx.x;
    if (tid <= NEXP) spoff[tid] = g_poff[tid];
    if (tid < NEXP) scnt[tid] = g_cnt[tid];
    __syncthreads();
    int m0 = blockIdx.y * 128;
    if (m0 >= spoff[NEXP]) return;
    int e = 0;
    while (m0 >= spoff[e + 1]) e++;
    int n0 = blockIdx.x * 128;
    int tx = tid & 15, ty = tid >> 4;
    int arow = tid >> 1, acol = (tid & 1) * 8;
    int brow = tid >> 4, bcol = (tid & 15) * 4;
    const float* aptr = g_hbuf + (size_t)(m0 + arow) * IDIM + acol;
    const float* bptr = Wd + (size_t)e * IDIM * HDIM + (size_t)brow * HDIM + n0;
    float4 ra0 = *(const float4*)(aptr);
    float4 ra1 = *(const float4*)(aptr + 4);
    float4 rb0 = *(const float4*)(bptr + bcol);
    float4 rb1 = *(const float4*)(bptr + 64 + bcol);
    float acc[8][8] = {};
    int buf = 0;
    for (int k0 = 0; k0 < IDIM; k0 += 16) {
        float* Asb = As[buf];
        float* Bsb = Bs[buf];
        Asb[(acol + 0) * 132 + arow] = ra0.x;
        Asb[(acol + 1) * 132 + arow] = ra0.y;
        Asb[(acol + 2) * 132 + arow] = ra0.z;
        Asb[(acol + 3) * 132 + arow] = ra0.w;
        Asb[(acol + 4) * 132 + arow] = ra1.x;
        Asb[(acol + 5) * 132 + arow] = ra1.y;
        Asb[(acol + 6) * 132 + arow] = ra1.z;
        Asb[(acol + 7) * 132 + arow] = ra1.w;
        *(float4*)&Bsb[brow * 128 + bcol] = rb0;
        *(float4*)&Bsb[brow * 128 + 64 + bcol] = rb1;
        __syncthreads();
        if (k0 + 16 < IDIM) {
            ra0 = *(const float4*)(aptr + k0 + 16);
            ra1 = *(const float4*)(aptr + k0 + 20);
            rb0 = *(const float4*)(bptr + (size_t)(k0 + 16) * HDIM + bcol);
            rb1 = *(const float4*)(bptr + (size_t)(k0 + 16) * HDIM + 64 + bcol);
        }
        #pragma unroll
        for (int k = 0; k < 16; k++) {
            float4 a0 = *(const float4*)&Asb[k * 132 + ty * 4];
            float4 a1 = *(const float4*)&Asb[k * 132 + 64 + ty * 4];
            float4 b0 = *(const float4*)&Bsb[k * 128 + tx * 4];
            float4 b1 = *(const float4*)&Bsb[k * 128 + 64 + tx * 4];
            float a[8] = {a0.x, a0.y, a0.z, a0.w, a1.x, a1.y, a1.z, a1.w};
            float b[8] = {b0.x, b0.y, b0.z, b0.w, b1.x, b1.y, b1.z, b1.w};
            #pragma unroll
            for (int i = 0; i < 8; i++)
                #pragma unroll
                for (int j = 0; j < 8; j++)
                    acc[i][j] = fmaf(a[i], b[j], acc[i][j]);
        }
        buf ^= 1;
    }
    #pragma unroll
    for (int ii = 0; ii < 2; ii++) {
        #pragma unroll
        for (int i = 0; i < 4; i++) {
            int ai = ii * 4 + i;
            int m = m0 + ii * 64 + ty * 4 + i;
            if ((m - spoff[e]) < scnt[e]) {
                int enc = g_list[m];  // 2*token + slot
                float* crow = g_slot + (size_t)enc * HDIM + n0;
                float4 r0 = {acc[ai][0], acc[ai][1], acc[ai][2], acc[ai][3]};
                float4 r1 = {acc[ai][4], acc[ai][5], acc[ai][6], acc[ai][7]};
                *(float4*)(crow + tx * 4) = r0;
                *(float4*)(crow + 64 + tx * 4) = r1;
            }
        }
    }
}

// ---------------- final combine: out = x1 + shared + w0*slot0 + w1*slot1 --------
__global__ void combine_kernel(float* __restrict__ out) {
    int i = blockIdx.x * blockDim.x + threadIdx.x;  // over TT*HDIM/4
    if (i >= TT * HDIM / 4) return;
    int c = i & (HDIM / 4 - 1);
    int t = i / (HDIM / 4);
    float w0 = g_topwt[2 * t], w1 = g_topwt[2 * t + 1];
    float4 a = ((const float4*)g_x1)[i];
    float4 sh = ((const float4*)g_sharedo)[i];
    float4 s0 = ((const float4*)g_slot)[(size_t)(2 * t) * (HDIM / 4) + c];
    float4 s1 = ((const float4*)g_slot)[(size_t)(2 * t + 1) * (HDIM / 4) + c];
    float4 r;
    r.x = a.x + sh.x + w0 * s0.x + w1 * s1.x;
    r.y = a.y + sh.y + w0 * s0.y + w1 * s1.y;
    r.z = a.z + sh.z + w0 * s0.z + w1 * s1.z;
    r.w = a.w + sh.w + w0 * s0.w + w1 * s1.w;
    ((float4*)out)[i] = r;
}

// ================================ host launcher =================================
static float* sym_f(const void* s) {
    void* p = nullptr;
    cudaGetSymbolAddress(&p, s);
    return (float*)p;
}

extern "C" void kernel_launch(void* const* d_in, const int* in_sizes, int n_in,
                              void* d_out, int out_size) {
    const float* x        = (const float*)d_in[0];
    const float* w_ln1    = (const float*)d_in[1];
    const float* w_ln2    = (const float*)d_in[2];
    const float* W_kvd    = (const float*)d_in[3];
    const float* W_qd     = (const float*)d_in[4];
    const float* W_ku     = (const float*)d_in[5];
    const float* W_qu     = (const float*)d_in[6];
    const float* W_vu     = (const float*)d_in[7];
    const float* W_ropeq  = (const float*)d_in[8];
    const float* W_ropek  = (const float*)d_in[9];
    const float* W_o      = (const float*)d_in[10];
    const float* Wg_s     = (const float*)d_in[11];
    const float* Wu_s     = (const float*)d_in[12];
    const float* Wd_s     = (const float*)d_in[13];
    const float* Wg_r     = (const float*)d_in[14];
    const float* Wu_r     = (const float*)d_in[15];
    const float* Wd_r     = (const float*)d_in[16];
    const float* W_router = (const float*)d_in[17];
    const float* r_bias   = (const float*)d_in[18];
    float* out = (float*)d_out;

    float* xn1    = sym_f(g_xn1);
    float* kvlat  = sym_f(g_kvlat);
    float* qlat   = sym_f(g_qlat);
    float* khalf  = sym_f(g_khalf);
    float* qhalf  = sym_f(g_qhalf);
    float* qropeb = sym_f(g_qropeb);
    float* kropeb = sym_f(g_kropeb);
    float* vbuf   = sym_f(g_v);
    float* ybuf   = sym_f(g_y);
    float* x1     = sym_f(g_x1);
    float* xn2    = sym_f(g_xn2);
    float* hmids  = sym_f(g_hmids);
    float* sharedo = sym_f(g_sharedo);

    static const int FLASH_SMEM = (4096 * 3 + 64 * 65) * 4;  // 65792 B
    cudaFuncSetAttribute(flash_kernel, cudaFuncAttributeMaxDynamicSharedMemorySize,
                         FLASH_SMEM);

    // ---- MLA ----
    rmsnorm_kernel<<<TT, 256>>>(x, w_ln1, xn1);
    sgemm128_kernel<<<dim3(LAT / 128, TT / 128), 256>>>(xn1, W_kvd, nullptr, kvlat, TT, LAT, HDIM);
    sgemm128_kernel<<<dim3(LAT / 128, TT / 128), 256>>>(xn1, W_qd, nullptr, qlat, TT, LAT, HDIM);
    sgemm128_kernel<<<dim3(512 / 128, TT / 128), 256>>>(kvlat, W_ku, nullptr, khalf, TT, 512, LAT);
    sgemm128_kernel<<<dim3(512 / 128, TT / 128), 256>>>(qlat, W_qu, nullptr, qhalf, TT, 512, LAT);
    sgemm128_kernel<<<dim3(HDIM / 128, TT / 128), 256>>>(kvlat, W_vu, nullptr, vbuf, TT, HDIM, LAT);
    sgemm128_kernel<<<dim3(512 / 128, TT / 128), 256>>>(qlat, W_ropeq, nullptr, qropeb, TT, 512, LAT);
    sgemm128_kernel<<<dim3(512 / 128, TT / 128), 256>>>(xn1, W_ropek, nullptr, kropeb, TT, 512, HDIM);
    {
        int n = TT * NHEAD * HH;
        rope_concat_kernel<<<(n + 255) / 256, 256>>>();
    }
    flash_kernel<<<dim3(SS / 64, NHEAD, BB), 256, FLASH_SMEM>>>();
    // x1 = x + y @ W_o
    sgemm128_kernel<<<dim3(HDIM / 128, TT / 128), 256>>>(ybuf, W_o, x, x1, TT, HDIM, HDIM);

    // ---- MoE ----
    rmsnorm_kernel<<<TT, 256>>>(x1, w_ln2, xn2);
    zero_cnt_kernel<<<1, 32>>>();
    router_kernel<<<TT / 4, 128>>>(W_router, r_bias);
    prefix_kernel<<<1, 32>>>();
    scatter_kernel<<<(TT + 255) / 256, 256>>>();
    // shared expert
    dual128_kernel<<<dim3(IDIM / 64, TT / 128), 256>>>(xn2, Wg_s, Wu_s, hmids,
                                                       TT, IDIM, HDIM);
    sgemm128_kernel<<<dim3(HDIM / 128, TT / 128), 256>>>(hmids, Wd_s, nullptr, sharedo,
                                                         TT, HDIM, IDIM);
    // routed experts (sparse, padded 128-row segments)
    routed_up_kernel<<<dim3(IDIM / 64, HBUF_ROWS / 128), 256>>>(Wg_r, Wu_r);
    routed_down_kernel<<<dim3(HDIM / 128, HBUF_ROWS / 128), 256>>>(Wd_r);
    // out = x1 + shared + weighted routed
    combine_kernel<<<(TT * HDIM / 4 + 255) / 256, 256>>>(out);
}

// round 5
// speedup vs baseline: 1.7168x; 1.5424x over previous
#include <cuda_runtime.h>
#include <math.h>
#include <stdint.h>

// Problem constants
#define HDIM 1024
#define NHEAD 16
#define HD 64
#define HH 32
#define LAT 256
#define IDIM 1024
#define NEXP 7
#define BB 4
#define SS 1024
#define TT 4096            // BB*SS tokens
#define HBUF_ROWS 9216     // padded routed rows (2*TT + 7*127, rounded to 128)

// TF32 MMA tile geometry
#define AS_STRIDE 36               // 128 x 32 A tile, k-contig rows, pad to 36
#define AS_TILE (128 * AS_STRIDE)  // 4608 floats
#define BS_STRIDE 132              // 32 x 128 B tile, n-contig rows, pad to 132
#define BS_TILE (32 * BS_STRIDE)   // 4224 floats
#define MMT_SMEM ((2 * (AS_TILE + BS_TILE)) * 4)  // 70656 bytes

// ---------------- scratch (device globals; no allocation allowed) ----------------
__device__ float g_xn1[TT * HDIM];
__device__ float g_kvlat[TT * LAT];
__device__ float g_qlat[TT * LAT];
__device__ float g_khalf[TT * NHEAD * HH];
__device__ float g_qhalf[TT * NHEAD * HH];
__device__ float g_qropeb[TT * NHEAD * HH];
__device__ float g_kropeb[TT * NHEAD * HH];
__device__ float g_v[TT * HDIM];
__device__ float g_kk[TT * HDIM];
__device__ float g_qq[TT * HDIM];
__device__ float g_y[TT * HDIM];
__device__ float g_x1[TT * HDIM];
__device__ float g_xn2[TT * HDIM];
__device__ float g_hmids[TT * IDIM];
__device__ float g_hmidu[TT * IDIM];
__device__ float g_sharedo[TT * HDIM];
__device__ float g_hbuf[HBUF_ROWS * IDIM];
__device__ float g_hbufu[HBUF_ROWS * IDIM];
__device__ float g_slot[TT * 2 * HDIM];
__device__ int   g_topidx[TT * 2];
__device__ float g_topwt[TT * 2];
__device__ int   g_cnt[NEXP];
__device__ int   g_poff[NEXP + 1];
__device__ int   g_fill[NEXP];
__device__ int   g_list[HBUF_ROWS];

__device__ __forceinline__ float silu_f(float g) {
    return g / (1.0f + __expf(-g));
}

__device__ __forceinline__ unsigned f2tf(float f) {
    unsigned r;
    asm("cvt.rna.tf32.f32 %0, %1;" : "=r"(r) : "f"(f));
    return r;
}

__device__ __forceinline__ void mma8(float* d, const unsigned* a, unsigned b0, unsigned b1) {
    asm volatile(
        "mma.sync.aligned.m16n8k8.row.col.f32.tf32.tf32.f32 "
        "{%0,%1,%2,%3}, {%4,%5,%6,%7}, {%8,%9}, {%0,%1,%2,%3};\n"
        : "+f"(d[0]), "+f"(d[1]), "+f"(d[2]), "+f"(d[3])
        : "r"(a[0]), "r"(a[1]), "r"(a[2]), "r"(a[3]), "r"(b0), "r"(b1));
}

// ================= TF32 tensor-core GEMM: C = A[M,K] @ B[K,N] (+Dres) ===========
// MODE 0: plain (optional Dres residual add)
// MODE 1: MoE gather — A rows gathered from token list, B expert-selected
// MODE 2: MoE scatter — A rows direct (hbuf), B expert-selected, C scattered
// BM=BN=128, BK=32, 256 threads, 8 warps each computing 32x64 via m16n8k8.
template <int MODE>
__global__ void __launch_bounds__(256) mmt_core(
    const float* __restrict__ A, const float* __restrict__ B,
    const float* __restrict__ Dres, float* __restrict__ C,
    int M, int N, int K) {
    extern __shared__ float smf[];
    __shared__ int spoff[NEXP + 1];
    __shared__ int scnt[NEXP];
    float* As = smf;
    float* Bsm = smf + 2 * AS_TILE;
    int tid = threadIdx.x, lane = tid & 31, wid = tid >> 5;
    int m0 = blockIdx.y * 128, n0 = blockIdx.x * 128;
    int e = 0;
    if (MODE != 0) {
        if (tid <= NEXP) spoff[tid] = g_poff[tid];
        if (tid < NEXP) scnt[tid] = g_cnt[tid];
        __syncthreads();
        if (m0 >= spoff[NEXP]) return;
        while (m0 >= spoff[e + 1]) e++;
        B += (size_t)e * K * N;
    }
    int wm = (wid & 3) * 32, wn = (wid >> 2) * 64;
    int arow = tid >> 1, acol = (tid & 1) * 16;
    int brow = tid >> 3, bcol = (tid & 7) * 16;
    const float* aptr;
    if (MODE == 1) {
        int grow = m0 + arow;
        int tok = ((grow - spoff[e]) < scnt[e]) ? (g_list[grow] >> 1) : 0;
        aptr = A + (size_t)tok * K + acol;
    } else {
        aptr = A + (size_t)(m0 + arow) * K + acol;
    }
    const float* bptr = B + (size_t)brow * N + n0 + bcol;

    float4 ra[4], rb[4];
    #pragma unroll
    for (int u = 0; u < 4; u++) {
        ra[u] = *(const float4*)(aptr + 4 * u);
        rb[u] = *(const float4*)(bptr + 4 * u);
    }
    float acc[2][8][4];
    #pragma unroll
    for (int mi = 0; mi < 2; mi++)
        #pragma unroll
        for (int nj = 0; nj < 8; nj++)
            #pragma unroll
            for (int q = 0; q < 4; q++) acc[mi][nj][q] = 0.f;

    int r = lane >> 2, c = lane & 3;
    int buf = 0;
    for (int k0 = 0; k0 < K; k0 += 32) {
        float* Asb = As + buf * AS_TILE;
        float* Bsb = Bsm + buf * BS_TILE;
        #pragma unroll
        for (int u = 0; u < 4; u++) {
            uint4 ta = {f2tf(ra[u].x), f2tf(ra[u].y), f2tf(ra[u].z), f2tf(ra[u].w)};
            uint4 tb = {f2tf(rb[u].x), f2tf(rb[u].y), f2tf(rb[u].z), f2tf(rb[u].w)};
            *(uint4*)&Asb[arow * AS_STRIDE + acol + 4 * u] = ta;
            *(uint4*)&Bsb[brow * BS_STRIDE + bcol + 4 * u] = tb;
        }
        __syncthreads();
        // NOTE: single barrier per K-step. This sync (after stores to buf)
        // also guarantees every thread has finished the PREVIOUS iteration's
        // compute (compute_{i-1} precedes store_i in program order), so the
        // next iteration may safely store into buf^1 with no second barrier.
        if (k0 + 32 < K) {
            #pragma unroll
            for (int u = 0; u < 4; u++) {
                ra[u] = *(const float4*)(aptr + k0 + 32 + 4 * u);
                rb[u] = *(const float4*)(bptr + (size_t)(k0 + 32) * N + 4 * u);
            }
        }
        #pragma unroll
        for (int ks = 0; ks < 4; ks++) {
            int kk = ks * 8;
            unsigned af[2][4];
            #pragma unroll
            for (int mi = 0; mi < 2; mi++) {
                const float* ab = Asb + (wm + mi * 16 + r) * AS_STRIDE + kk + c;
                af[mi][0] = __float_as_uint(ab[0]);
                af[mi][1] = __float_as_uint(ab[8 * AS_STRIDE]);
                af[mi][2] = __float_as_uint(ab[4]);
                af[mi][3] = __float_as_uint(ab[8 * AS_STRIDE + 4]);
            }
            #pragma unroll
            for (int nj = 0; nj < 8; nj++) {
                const float* bb = Bsb + (kk + c) * BS_STRIDE + wn + nj * 8 + r;
                unsigned b0 = __float_as_uint(bb[0]);
                unsigned b1 = __float_as_uint(bb[4 * BS_STRIDE]);
                mma8(acc[0][nj], af[0], b0, b1);
                mma8(acc[1][nj], af[1], b0, b1);
            }
        }
        buf ^= 1;
    }
    // epilogue: per (mi, half) the row is m0+wm+mi*16+r(+8); cols 2c,2c+1 per n-frag
    #pragma unroll
    for (int mi = 0; mi < 2; mi++) {
        #pragma unroll
        for (int h = 0; h < 2; h++) {
            int m = m0 + wm + mi * 16 + r + h * 8;
            if (MODE == 2) {
                if ((m - spoff[e]) >= scnt[e]) continue;
                int enc = g_list[m];  // 2*token + slot
                float* crow = C + (size_t)enc * N + n0 + wn;
                #pragma unroll
                for (int nj = 0; nj < 8; nj++) {
                    float2 v = {acc[mi][nj][h * 2], acc[mi][nj][h * 2 + 1]};
                    *(float2*)(crow + nj * 8 + c * 2) = v;
                }
            } else {
                float* crow = C + (size_t)m * N + n0 + wn;
                const float* drow = Dres ? (Dres + (size_t)m * N + n0 + wn) : nullptr;
                #pragma unroll
                for (int nj = 0; nj < 8; nj++) {
                    float2 v = {acc[mi][nj][h * 2], acc[mi][nj][h * 2 + 1]};
                    if (MODE == 0 && drow) {
                        float2 d = *(const float2*)(drow + nj * 8 + c * 2);
                        v.x += d.x; v.y += d.y;
                    }
                    *(float2*)(crow + nj * 8 + c * 2) = v;
                }
            }
        }
    }
}

// ---------------- elementwise: g = silu(g) * u ----------------------------------
__global__ void silumul_kernel(float* __restrict__ g, const float* __restrict__ u,
                               int n4) {
    int i = blockIdx.x * blockDim.x + threadIdx.x;
    if (i >= n4) return;
    float4 gv = ((float4*)g)[i];
    float4 uv = ((const float4*)u)[i];
    gv.x = silu_f(gv.x) * uv.x;
    gv.y = silu_f(gv.y) * uv.y;
    gv.z = silu_f(gv.z) * uv.z;
    gv.w = silu_f(gv.w) * uv.w;
    ((float4*)g)[i] = gv;
}

// ---------------- rmsnorm: norm = sqrt(mean(x^2)) + eps; y = x/norm * w ----------
__global__ void rmsnorm_kernel(const float* __restrict__ x,
                               const float* __restrict__ w,
                               float* __restrict__ out) {
    int t = blockIdx.x;
    const float* xr = x + (size_t)t * HDIM;
    float ss = 0.f;
    for (int h = threadIdx.x; h < HDIM; h += blockDim.x) {
        float v = xr[h];
        ss += v * v;
    }
    __shared__ float red[32];
    #pragma unroll
    for (int o = 16; o; o >>= 1) ss += __shfl_xor_sync(0xffffffffu, ss, o);
    if ((threadIdx.x & 31) == 0) red[threadIdx.x >> 5] = ss;
    __syncthreads();
    if (threadIdx.x < 32) {
        float v = (threadIdx.x < (blockDim.x >> 5)) ? red[threadIdx.x] : 0.f;
        #pragma unroll
        for (int o = 16; o; o >>= 1) v += __shfl_xor_sync(0xffffffffu, v, o);
        if (threadIdx.x == 0) red[0] = v;
    }
    __syncthreads();
    float inv = 1.0f / (sqrtf(red[0] * (1.0f / HDIM)) + 1e-5f);
    float* orow = out + (size_t)t * HDIM;
    for (int h = threadIdx.x; h < HDIM; h += blockDim.x)
        orow[h] = xr[h] * inv * w[h];
}

// ---------------- RoPE + concat into qq/kk [T, NH, 64] --------------------------
__global__ void rope_concat_kernel() {
    int i = blockIdx.x * blockDim.x + threadIdx.x;  // over TT*NHEAD*HH
    if (i >= TT * NHEAD * HH) return;
    int d = i & 31;
    int h = (i >> 5) & 15;
    int t = i >> 9;
    int s = t & (SS - 1);
    int j = d & 15;
    float invf = expf(-((float)j / 16.0f) * 9.210340371976184f);  // ln(10000)
    float ang = (float)s * invf;
    float c = cosf(ang), sn = sinf(ang);
    int o = t * HDIM + h * HD + d;
    float kr = g_kropeb[i];
    float krot = (d < 16) ? -g_kropeb[i + 16] : g_kropeb[i - 16];
    g_kk[o] = g_khalf[i];
    g_kk[o + HH] = kr * c + krot * sn;
    float qr = g_qropeb[i];
    float qrot = (d < 16) ? -g_qropeb[i + 16] : g_qropeb[i - 16];
    g_qq[o] = g_qhalf[i];
    g_qq[o + HH] = qr * c + qrot * sn;
}

// ---------------- flash attention: causal, 64x64 tiles, d=64 --------------------
__global__ void __launch_bounds__(256) flash_kernel() {
    extern __shared__ float sm[];
    float* Qst = sm;             // [d][q] 64x64, Q scaled by 1/8
    float* Kst = sm + 4096;      // [d][k] 64x64
    float* Vs  = sm + 8192;      // [k][d] 64x64
    float* Pst = sm + 12288;     // [k][q] 64x65 (padded)
    int qt = blockIdx.x, h = blockIdx.y, b = blockIdx.z;
    int tid = threadIdx.x;
    int tx = tid & 15, ty = tid >> 4;
    {
        int r = tid >> 2;
        int c0 = (tid & 3) << 4;
        const float* src = g_qq + ((size_t)(b * SS + qt * 64 + r)) * HDIM + h * HD + c0;
        #pragma unroll
        for (int u = 0; u < 4; u++) {
            float4 v4 = *(const float4*)(src + u * 4);
            Qst[(c0 + u * 4 + 0) * 64 + r] = v4.x * 0.125f;
            Qst[(c0 + u * 4 + 1) * 64 + r] = v4.y * 0.125f;
            Qst[(c0 + u * 4 + 2) * 64 + r] = v4.z * 0.125f;
            Qst[(c0 + u * 4 + 3) * 64 + r] = v4.w * 0.125f;
        }
    }
    float o[4][4] = {};
    float m_i[4], l_i[4];
    #pragma unroll
    for (int i = 0; i < 4; i++) { m_i[i] = -3.4e38f; l_i[i] = 0.f; }

    for (int kt = 0; kt <= qt; kt++) {
        __syncthreads();
        {
            int r = tid >> 2;
            int c0 = (tid & 3) << 4;
            const float* ks = g_kk + ((size_t)(b * SS + kt * 64 + r)) * HDIM + h * HD + c0;
            const float* vs = g_v + ((size_t)(b * SS + kt * 64 + r)) * HDIM + h * HD + c0;
            #pragma unroll
            for (int u = 0; u < 4; u++) {
                float4 v4 = *(const float4*)(ks + u * 4);
                Kst[(c0 + u * 4 + 0) * 64 + r] = v4.x;
                Kst[(c0 + u * 4 + 1) * 64 + r] = v4.y;
                Kst[(c0 + u * 4 + 2) * 64 + r] = v4.z;
                Kst[(c0 + u * 4 + 3) * 64 + r] = v4.w;
                *(float4*)&Vs[r * 64 + c0 + u * 4] = *(const float4*)(vs + u * 4);
            }
        }
        __syncthreads();
        float s[4][4] = {};
        #pragma unroll 4
        for (int d = 0; d < 64; d++) {
            float4 a4 = *(const float4*)&Qst[d * 64 + ty * 4];
            float4 b4 = *(const float4*)&Kst[d * 64 + tx * 4];
            float a[4] = {a4.x, a4.y, a4.z, a4.w};
            float bb[4] = {b4.x, b4.y, b4.z, b4.w};
            #pragma unroll
            for (int i = 0; i < 4; i++)
                #pragma unroll
                for (int j = 0; j < 4; j++)
                    s[i][j] = fmaf(a[i], bb[j], s[i][j]);
        }
        if (kt == qt) {
            #pragma unroll
            for (int i = 0; i < 4; i++)
                #pragma unroll
                for (int j = 0; j < 4; j++)
                    if (tx * 4 + j > ty * 4 + i) s[i][j] = -3.4e38f;
        }
        #pragma unroll
        for (int i = 0; i < 4; i++) {
            float mx = fmaxf(fmaxf(s[i][0], s[i][1]), fmaxf(s[i][2], s[i][3]));
            #pragma unroll
            for (int off = 8; off; off >>= 1)
                mx = fmaxf(mx, __shfl_xor_sync(0xffffffffu, mx, off));
            float mnew = fmaxf(m_i[i], mx);
            float alpha = __expf(m_i[i] - mnew);
            float rsum = 0.f;
            #pragma unroll
            for (int j = 0; j < 4; j++) {
                float p = __expf(s[i][j] - mnew);
                s[i][j] = p;
                rsum += p;
            }
            #pragma unroll
            for (int off = 8; off; off >>= 1)
                rsum += __shfl_xor_sync(0xffffffffu, rsum, off);
            l_i[i] = l_i[i] * alpha + rsum;
            m_i[i] = mnew;
            #pragma unroll
            for (int j = 0; j < 4; j++) {
                o[i][j] *= alpha;
                Pst[(tx * 4 + j) * 65 + ty * 4 + i] = s[i][j];
            }
        }
        __syncthreads();
        #pragma unroll 4
        for (int k = 0; k < 64; k++) {
            float a[4];
            #pragma unroll
            for (int i = 0; i < 4; i++) a[i] = Pst[k * 65 + ty * 4 + i];
            float4 b4 = *(const float4*)&Vs[k * 64 + tx * 4];
            float bb[4] = {b4.x, b4.y, b4.z, b4.w};
            #pragma unroll
            for (int i = 0; i < 4; i++)
                #pragma unroll
                for (int j = 0; j < 4; j++)
                    o[i][j] = fmaf(a[i], bb[j], o[i][j]);
        }
    }
    #pragma unroll
    for (int i = 0; i < 4; i++) {
        float inv = 1.0f / l_i[i];
        int q = qt * 64 + ty * 4 + i;
        float4 r = {o[i][0] * inv, o[i][1] * inv, o[i][2] * inv, o[i][3] * inv};
        *(float4*)(g_y + ((size_t)(b * SS + q)) * HDIM + h * HD + tx * 4) = r;
    }
}

// ---------------- router ---------------------------------------------------------
__global__ void zero_cnt_kernel() {
    if (threadIdx.x < NEXP) g_cnt[threadIdx.x] = 0;
}

__global__ void router_kernel(const float* __restrict__ Wr,
                              const float* __restrict__ bias) {
    int t = blockIdx.x * (blockDim.x >> 5) + (threadIdx.x >> 5);
    int lane = threadIdx.x & 31;
    if (t >= TT) return;
    const float* xr = g_xn2 + (size_t)t * HDIM;
    float acc[NEXP] = {};
    for (int h = lane; h < HDIM; h += 32) {
        float xv = xr[h];
        #pragma unroll
        for (int e = 0; e < NEXP; e++)
            acc[e] = fmaf(xv, Wr[h * NEXP + e], acc[e]);
    }
    #pragma unroll
    for (int e = 0; e < NEXP; e++)
        #pragma unroll
        for (int o = 16; o; o >>= 1)
            acc[e] += __shfl_xor_sync(0xffffffffu, acc[e], o);
    if (lane == 0) {
        float p[NEXP];
        #pragma unroll
        for (int e = 0; e < NEXP; e++)
            p[e] = 1.0f / (1.0f + expf(-(acc[e] + bias[e])));
        int i0 = 0;
        #pragma unroll
        for (int e = 1; e < NEXP; e++) if (p[e] > p[i0]) i0 = e;
        int i1 = (i0 == 0) ? 1 : 0;
        #pragma unroll
        for (int e = 0; e < NEXP; e++)
            if (e != i0 && p[e] > p[i1]) i1 = e;
        float ssum = p[i0] + p[i1];
        g_topidx[2 * t] = i0;
        g_topidx[2 * t + 1] = i1;
        g_topwt[2 * t] = p[i0] / ssum;
        g_topwt[2 * t + 1] = p[i1] / ssum;
        atomicAdd(&g_cnt[i0], 1);
        atomicAdd(&g_cnt[i1], 1);
    }
}

__global__ void prefix_kernel() {
    if (threadIdx.x == 0) {
        int off = 0;
        for (int e = 0; e < NEXP; e++) {
            g_poff[e] = off;
            off += (g_cnt[e] + 127) & ~127;   // pad segments to 128 rows
            g_fill[e] = 0;
        }
        g_poff[NEXP] = off;
    }
}

__global__ void scatter_kernel() {
    int t = blockIdx.x * blockDim.x + threadIdx.x;
    if (t >= TT) return;
    #pragma unroll
    for (int s = 0; s < 2; s++) {
        int e = g_topidx[2 * t + s];
        int pos = atomicAdd(&g_fill[e], 1);
        g_list[g_poff[e] + pos] = 2 * t + s;
    }
}

// ---------------- final combine: out = x1 + shared + w0*slot0 + w1*slot1 --------
__global__ void combine_kernel(float* __restrict__ out) {
    int i = blockIdx.x * blockDim.x + threadIdx.x;  // over TT*HDIM/4
    if (i >= TT * HDIM / 4) return;
    int c = i & (HDIM / 4 - 1);
    int t = i / (HDIM / 4);
    float w0 = g_topwt[2 * t], w1 = g_topwt[2 * t + 1];
    float4 a = ((const float4*)g_x1)[i];
    float4 sh = ((const float4*)g_sharedo)[i];
    float4 s0 = ((const float4*)g_slot)[(size_t)(2 * t) * (HDIM / 4) + c];
    float4 s1 = ((const float4*)g_slot)[(size_t)(2 * t + 1) * (HDIM / 4) + c];
    float4 r;
    r.x = a.x + sh.x + w0 * s0.x + w1 * s1.x;
    r.y = a.y + sh.y + w0 * s0.y + w1 * s1.y;
    r.z = a.z + sh.z + w0 * s0.z + w1 * s1.z;
    r.w = a.w + sh.w + w0 * s0.w + w1 * s1.w;
    ((float4*)out)[i] = r;
}

// ================================ host launcher =================================
static float* sym_f(const void* s) {
    void* p = nullptr;
    cudaGetSymbolAddress(&p, s);
    return (float*)p;
}

extern "C" void kernel_launch(void* const* d_in, const int* in_sizes, int n_in,
                              void* d_out, int out_size) {
    const float* x        = (const float*)d_in[0];
    const float* w_ln1    = (const float*)d_in[1];
    const float* w_ln2    = (const float*)d_in[2];
    const float* W_kvd    = (const float*)d_in[3];
    const float* W_qd     = (const float*)d_in[4];
    const float* W_ku     = (const float*)d_in[5];
    const float* W_qu     = (const float*)d_in[6];
    const float* W_vu     = (const float*)d_in[7];
    const float* W_ropeq  = (const float*)d_in[8];
    const float* W_ropek  = (const float*)d_in[9];
    const float* W_o      = (const float*)d_in[10];
    const float* Wg_s     = (const float*)d_in[11];
    const float* Wu_s     = (const float*)d_in[12];
    const float* Wd_s     = (const float*)d_in[13];
    const float* Wg_r     = (const float*)d_in[14];
    const float* Wu_r     = (const float*)d_in[15];
    const float* Wd_r     = (const float*)d_in[16];
    const float* W_router = (const float*)d_in[17];
    const float* r_bias   = (const float*)d_in[18];
    float* out = (float*)d_out;

    float* xn1    = sym_f(g_xn1);
    float* kvlat  = sym_f(g_kvlat);
    float* qlat   = sym_f(g_qlat);
    float* khalf  = sym_f(g_khalf);
    float* qhalf  = sym_f(g_qhalf);
    float* qropeb = sym_f(g_qropeb);
    float* kropeb = sym_f(g_kropeb);
    float* vbuf   = sym_f(g_v);
    float* ybuf   = sym_f(g_y);
    float* x1     = sym_f(g_x1);
    float* xn2    = sym_f(g_xn2);
    float* hmids  = sym_f(g_hmids);
    float* hmidu  = sym_f(g_hmidu);
    float* sharedo = sym_f(g_sharedo);
    float* hbuf   = sym_f(g_hbuf);
    float* hbufu  = sym_f(g_hbufu);
    float* slot   = sym_f(g_slot);

    static const int FLASH_SMEM = (4096 * 3 + 64 * 65) * 4;  // 65792 B
    cudaFuncSetAttribute(flash_kernel, cudaFuncAttributeMaxDynamicSharedMemorySize,
                         FLASH_SMEM);
    cudaFuncSetAttribute(mmt_core<0>, cudaFuncAttributeMaxDynamicSharedMemorySize,
                         MMT_SMEM);
    cudaFuncSetAttribute(mmt_core<1>, cudaFuncAttributeMaxDynamicSharedMemorySize,
                         MMT_SMEM);
    cudaFuncSetAttribute(mmt_core<2>, cudaFuncAttributeMaxDynamicSharedMemorySize,
                         MMT_SMEM);

    #define MMT(Ap, Bp, Dp, Cp, M, N, K) \
        mmt_core<0><<<dim3((N) / 128, (M) / 128), 256, MMT_SMEM>>>(Ap, Bp, Dp, Cp, M, N, K)

    // ---- MLA ----
    rmsnorm_kernel<<<TT, 256>>>(x, w_ln1, xn1);
    MMT(xn1, W_kvd, nullptr, kvlat, TT, LAT, HDIM);
    MMT(xn1, W_qd, nullptr, qlat, TT, LAT, HDIM);
    MMT(kvlat, W_ku, nullptr, khalf, TT, 512, LAT);
    MMT(qlat, W_qu, nullptr, qhalf, TT, 512, LAT);
    MMT(kvlat, W_vu, nullptr, vbuf, TT, HDIM, LAT);
    MMT(qlat, W_ropeq, nullptr, qropeb, TT, 512, LAT);
    MMT(xn1, W_ropek, nullptr, kropeb, TT, 512, HDIM);
    {
        int n = TT * NHEAD * HH;
        rope_concat_kernel<<<(n + 255) / 256, 256>>>();
    }
    flash_kernel<<<dim3(SS / 64, NHEAD, BB), 256, FLASH_SMEM>>>();
    // x1 = x + y @ W_o
    MMT(ybuf, W_o, x, x1, TT, HDIM, HDIM);

    // ---- MoE ----
    rmsnorm_kernel<<<TT, 256>>>(x1, w_ln2, xn2);
    zero_cnt_kernel<<<1, 32>>>();
    router_kernel<<<TT / 4, 128>>>(W_router, r_bias);
    prefix_kernel<<<1, 32>>>();
    scatter_kernel<<<(TT + 255) / 256, 256>>>();
    // shared expert: two tf32 GEMMs + silu-mul + down GEMM
    MMT(xn2, Wg_s, nullptr, hmids, TT, IDIM, HDIM);
    MMT(xn2, Wu_s, nullptr, hmidu, TT, IDIM, HDIM);
    silumul_kernel<<<(TT * IDIM / 4 + 255) / 256, 256>>>(hmids, hmidu, TT * IDIM / 4);
    MMT(hmids, Wd_s, nullptr, sharedo, TT, HDIM, IDIM);
    // routed experts (sparse, padded 128-row segments)
    mmt_core<1><<<dim3(IDIM / 128, HBUF_ROWS / 128), 256, MMT_SMEM>>>(
        xn2, Wg_r, nullptr, hbuf, HBUF_ROWS, IDIM, HDIM);
    mmt_core<1><<<dim3(IDIM / 128, HBUF_ROWS / 128), 256, MMT_SMEM>>>(
        xn2, Wu_r, nullptr, hbufu, HBUF_ROWS, IDIM, HDIM);
    silumul_kernel<<<(HBUF_ROWS * IDIM / 4 + 255) / 256, 256>>>(
        hbuf, hbufu, HBUF_ROWS * IDIM / 4);
    mmt_core<2><<<dim3(HDIM / 128, HBUF_ROWS / 128), 256, MMT_SMEM>>>(
        hbuf, Wd_r, nullptr, slot, HBUF_ROWS, HDIM, IDIM);
    // out = x1 + shared + weighted routed
    combine_kernel<<<(TT * HDIM / 4 + 255) / 256, 256>>>(out);
}

// round 7
// speedup vs baseline: 2.0810x; 1.2121x over previous
#include <cuda_runtime.h>
#include <math.h>
#include <stdint.h>

// Problem constants
#define HDIM 1024
#define NHEAD 16
#define HD 64
#define HH 32
#define LAT 256
#define IDIM 1024
#define NEXP 7
#define BB 4
#define SS 1024
#define TT 4096            // BB*SS tokens
#define HBUF_ROWS 9216     // padded routed rows (2*TT + 7*127, rounded to 128)

// TF32 MMA pipeline geometry: BM=BN=128, BK=16, 4 stages
#define ASTR 20                    // A stage: 128 rows x 16 k, stride 20 (80B, 16B-mult)
#define BSTR 136                   // B stage: 16 k x 128 n, stride 136 (544B, 16B-mult)
#define A_ST (128 * ASTR)          // 2560 floats
#define B_ST (16 * BSTR)           // 2176 floats
#define STAGE_F (A_ST + B_ST)      // 4736 floats
#define NSTAGE 4
#define MMT_SMEM (NSTAGE * STAGE_F * 4)   // 75776 bytes

// ---------------- scratch (device globals; no allocation allowed) ----------------
__device__ float g_xn1[TT * HDIM];
__device__ float g_kvlat[TT * LAT];
__device__ float g_qlat[TT * LAT];
__device__ float g_khalf[TT * NHEAD * HH];
__device__ float g_qhalf[TT * NHEAD * HH];
__device__ float g_qropeb[TT * NHEAD * HH];
__device__ float g_kropeb[TT * NHEAD * HH];
__device__ float g_v[TT * HDIM];
__device__ float g_kk[TT * HDIM];
__device__ float g_qq[TT * HDIM];
__device__ float g_y[TT * HDIM];
__device__ float g_x1[TT * HDIM];
__device__ float g_xn2[TT * HDIM];
__device__ float g_hmids[TT * IDIM];
__device__ float g_hmidu[TT * IDIM];
__device__ float g_sharedo[TT * HDIM];
__device__ float g_hbuf[HBUF_ROWS * IDIM];
__device__ float g_hbufu[HBUF_ROWS * IDIM];
__device__ float g_slot[TT * 2 * HDIM];
__device__ int   g_topidx[TT * 2];
__device__ float g_topwt[TT * 2];
__device__ int   g_cnt[NEXP];
__device__ int   g_poff[NEXP + 1];
__device__ int   g_fill[NEXP];
__device__ int   g_list[HBUF_ROWS];

__device__ __forceinline__ float silu_f(float g) {
    return g / (1.0f + __expf(-g));
}

__device__ __forceinline__ void cpa16(uint32_t dst, const void* src) {
    asm volatile("cp.async.ca.shared.global [%0], [%1], 16;\n" :: "r"(dst), "l"(src));
}
__device__ __forceinline__ void cpa_commit() {
    asm volatile("cp.async.commit_group;\n");
}
template <int N>
__device__ __forceinline__ void cpa_wait() {
    asm volatile("cp.async.wait_group %0;\n" :: "n"(N));
}

__device__ __forceinline__ void mma8(float* d, const unsigned* a, unsigned b0, unsigned b1) {
    asm volatile(
        "mma.sync.aligned.m16n8k8.row.col.f32.tf32.tf32.f32 "
        "{%0,%1,%2,%3}, {%4,%5,%6,%7}, {%8,%9}, {%0,%1,%2,%3};\n"
        : "+f"(d[0]), "+f"(d[1]), "+f"(d[2]), "+f"(d[3])
        : "r"(a[0]), "r"(a[1]), "r"(a[2]), "r"(a[3]), "r"(b0), "r"(b1));
}

// ================= TF32 tensor-core GEMM: C = A[M,K] @ B[K,N] (+Dres) ===========
// MODE 0: plain (optional Dres residual add)
// MODE 1: MoE gather — A rows gathered from token list, B expert-selected
// MODE 2: MoE scatter — A rows direct (hbuf), B expert-selected, C scattered
// BM=BN=128, BK=16, 4-stage cp.async pipeline, 256 threads (8 warps, 32x64 each).
// fp32 values fed to tf32 MMA without explicit cvt (HW uses tf32 bits).
template <int MODE>
__global__ void __launch_bounds__(256, 2) mmt_core(
    const float* __restrict__ A, const float* __restrict__ B,
    const float* __restrict__ Dres, float* __restrict__ C,
    int M, int N, int K) {
    extern __shared__ float smf[];
    __shared__ int spoff[NEXP + 1];
    __shared__ int scnt[NEXP];
    int tid = threadIdx.x, lane = tid & 31, wid = tid >> 5;
    int m0 = blockIdx.y * 128, n0 = blockIdx.x * 128;
    int e = 0;
    if (MODE != 0) {
        if (tid <= NEXP) spoff[tid] = g_poff[tid];
        if (tid < NEXP) scnt[tid] = g_cnt[tid];
        __syncthreads();
        if (m0 >= spoff[NEXP]) return;
        while (m0 >= spoff[e + 1]) e++;
        B += (size_t)e * K * N;
    }
    int wm = (wid & 3) * 32, wn = (wid >> 2) * 64;
    // loader mapping
    int arow = tid >> 1, ahalf = (tid & 1) * 8;   // A: 128 rows x 16 k (2x16B per thread)
    int brow = tid >> 4, bcol = (tid & 15) * 8;   // B: 16 k x 128 n  (2x16B per thread)
    const float* asrc;
    if (MODE == 1) {
        int grow = m0 + arow;
        int tok = ((grow - spoff[e]) < scnt[e]) ? (g_list[grow] >> 1) : 0;
        asrc = A + (size_t)tok * K + ahalf;
    } else {
        asrc = A + (size_t)(m0 + arow) * K + ahalf;
    }
    const float* bsrc = B + (size_t)brow * N + n0 + bcol;

    uint32_t smem_u = (uint32_t)__cvta_generic_to_shared(smf);
    uint32_t a_dst0 = smem_u + (arow * ASTR + ahalf) * 4;
    uint32_t b_dst0 = smem_u + (A_ST + brow * BSTR + bcol) * 4;

    float acc[2][8][4];
    #pragma unroll
    for (int mi = 0; mi < 2; mi++)
        #pragma unroll
        for (int nj = 0; nj < 8; nj++)
            #pragma unroll
            for (int q = 0; q < 4; q++) acc[mi][nj][q] = 0.f;

    int kiters = K >> 4;
    // prologue: stages 0..NSTAGE-2
    #pragma unroll
    for (int s = 0; s < NSTAGE - 1; s++) {
        int k0 = s * 16;
        uint32_t so = s * (STAGE_F * 4);
        cpa16(a_dst0 + so, asrc + k0);
        cpa16(a_dst0 + so + 16, asrc + k0 + 4);
        cpa16(b_dst0 + so, bsrc + (size_t)k0 * N);
        cpa16(b_dst0 + so + 16, bsrc + (size_t)k0 * N + 4);
        cpa_commit();
    }

    int r = lane >> 2, c = lane & 3;
    for (int it = 0; it < kiters; it++) {
        cpa_wait<NSTAGE - 2>();
        __syncthreads();
        // issue stage it+NSTAGE-1 (overwrites stage computed in iter it-1; safe
        // because the sync above means every thread finished that compute)
        int nk = it + NSTAGE - 1;
        if (nk < kiters) {
            int s = nk & (NSTAGE - 1);
            int k0 = nk * 16;
            uint32_t so = s * (STAGE_F * 4);
            cpa16(a_dst0 + so, asrc + k0);
            cpa16(a_dst0 + so + 16, asrc + k0 + 4);
            cpa16(b_dst0 + so, bsrc + (size_t)k0 * N);
            cpa16(b_dst0 + so + 16, bsrc + (size_t)k0 * N + 4);
        }
        cpa_commit();  // commit each iter (possibly empty) to keep group count uniform

        const float* Asb = smf + (it & (NSTAGE - 1)) * STAGE_F;
        const float* Bsb = Asb + A_ST;
        #pragma unroll
        for (int ks = 0; ks < 2; ks++) {
            int kk = ks * 8;
            unsigned af[2][4];
            #pragma unroll
            for (int mi = 0; mi < 2; mi++) {
                const float* ab = Asb + (wm + mi * 16 + r) * ASTR + kk + c;
                af[mi][0] = __float_as_uint(ab[0]);
                af[mi][1] = __float_as_uint(ab[8 * ASTR]);
                af[mi][2] = __float_as_uint(ab[4]);
                af[mi][3] = __float_as_uint(ab[8 * ASTR + 4]);
            }
            #pragma unroll
            for (int nj = 0; nj < 8; nj++) {
                const float* bb = Bsb + (kk + c) * BSTR + wn + nj * 8 + r;
                unsigned b0 = __float_as_uint(bb[0]);
                unsigned b1 = __float_as_uint(bb[4 * BSTR]);
                mma8(acc[0][nj], af[0], b0, b1);
                mma8(acc[1][nj], af[1], b0, b1);
            }
        }
    }
    // epilogue: per (mi, half) row = m0+wm+mi*16+r(+8); cols 2c,2c+1 per n-frag
    #pragma unroll
    for (int mi = 0; mi < 2; mi++) {
        #pragma unroll
        for (int h = 0; h < 2; h++) {
            int m = m0 + wm + mi * 16 + r + h * 8;
            if (MODE == 2) {
                if ((m - spoff[e]) >= scnt[e]) continue;
                int enc = g_list[m];  // 2*token + slot
                float* crow = C + (size_t)enc * N + n0 + wn;
                #pragma unroll
                for (int nj = 0; nj < 8; nj++) {
                    float2 v = {acc[mi][nj][h * 2], acc[mi][nj][h * 2 + 1]};
                    *(float2*)(crow + nj * 8 + c * 2) = v;
                }
            } else {
                float* crow = C + (size_t)m * N + n0 + wn;
                const float* drow = Dres ? (Dres + (size_t)m * N + n0 + wn) : nullptr;
                #pragma unroll
                for (int nj = 0; nj < 8; nj++) {
                    float2 v = {acc[mi][nj][h * 2], acc[mi][nj][h * 2 + 1]};
                    if (MODE == 0 && drow) {
                        float2 d = *(const float2*)(drow + nj * 8 + c * 2);
                        v.x += d.x; v.y += d.y;
                    }
                    *(float2*)(crow + nj * 8 + c * 2) = v;
                }
            }
        }
    }
}

// ---------------- elementwise: g = silu(g) * u ----------------------------------
__global__ void silumul_kernel(float* __restrict__ g, const float* __restrict__ u,
                               int n4) {
    int i = blockIdx.x * blockDim.x + threadIdx.x;
    if (i >= n4) return;
    float4 gv = ((float4*)g)[i];
    float4 uv = ((const float4*)u)[i];
    gv.x = silu_f(gv.x) * uv.x;
    gv.y = silu_f(gv.y) * uv.y;
    gv.z = silu_f(gv.z) * uv.z;
    gv.w = silu_f(gv.w) * uv.w;
    ((float4*)g)[i] = gv;
}

// ---------------- rmsnorm: norm = sqrt(mean(x^2)) + eps; y = x/norm * w ----------
__global__ void rmsnorm_kernel(const float* __restrict__ x,
                               const float* __restrict__ w,
                               float* __restrict__ out) {
    int t = blockIdx.x;
    const float* xr = x + (size_t)t * HDIM;
    float ss = 0.f;
    for (int h = threadIdx.x; h < HDIM; h += blockDim.x) {
        float v = xr[h];
        ss += v * v;
    }
    __shared__ float red[32];
    #pragma unroll
    for (int o = 16; o; o >>= 1) ss += __shfl_xor_sync(0xffffffffu, ss, o);
    if ((threadIdx.x & 31) == 0) red[threadIdx.x >> 5] = ss;
    __syncthreads();
    if (threadIdx.x < 32) {
        float v = (threadIdx.x < (blockDim.x >> 5)) ? red[threadIdx.x] : 0.f;
        #pragma unroll
        for (int o = 16; o; o >>= 1) v += __shfl_xor_sync(0xffffffffu, v, o);
        if (threadIdx.x == 0) red[0] = v;
    }
    __syncthreads();
    float inv = 1.0f / (sqrtf(red[0] * (1.0f / HDIM)) + 1e-5f);
    float* orow = out + (size_t)t * HDIM;
    for (int h = threadIdx.x; h < HDIM; h += blockDim.x)
        orow[h] = xr[h] * inv * w[h];
}

// ---------------- RoPE + concat into qq/kk [T, NH, 64] --------------------------
__global__ void rope_concat_kernel() {
    int i = blockIdx.x * blockDim.x + threadIdx.x;  // over TT*NHEAD*HH
    if (i >= TT * NHEAD * HH) return;
    int d = i & 31;
    int h = (i >> 5) & 15;
    int t = i >> 9;
    int s = t & (SS - 1);
    int j = d & 15;
    float invf = expf(-((float)j / 16.0f) * 9.210340371976184f);  // ln(10000)
    float ang = (float)s * invf;
    float c = cosf(ang), sn = sinf(ang);
    int o = t * HDIM + h * HD + d;
    float kr = g_kropeb[i];
    float krot = (d < 16) ? -g_kropeb[i + 16] : g_kropeb[i - 16];
    g_kk[o] = g_khalf[i];
    g_kk[o + HH] = kr * c + krot * sn;
    float qr = g_qropeb[i];
    float qrot = (d < 16) ? -g_qropeb[i + 16] : g_qropeb[i - 16];
    g_qq[o] = g_qhalf[i];
    g_qq[o + HH] = qr * c + qrot * sn;
}

// ---------------- flash attention: causal, 64x64 tiles, d=64 --------------------
__global__ void __launch_bounds__(256) flash_kernel() {
    extern __shared__ float sm[];
    float* Qst = sm;             // [d][q] 64x64, Q scaled by 1/8
    float* Kst = sm + 4096;      // [d][k] 64x64
    float* Vs  = sm + 8192;      // [k][d] 64x64
    float* Pst = sm + 12288;     // [k][q] 64x65 (padded)
    int qt = blockIdx.x, h = blockIdx.y, b = blockIdx.z;
    int tid = threadIdx.x;
    int tx = tid & 15, ty = tid >> 4;
    {
        int r = tid >> 2;
        int c0 = (tid & 3) << 4;
        const float* src = g_qq + ((size_t)(b * SS + qt * 64 + r)) * HDIM + h * HD + c0;
        #pragma unroll
        for (int u = 0; u < 4; u++) {
            float4 v4 = *(const float4*)(src + u * 4);
            Qst[(c0 + u * 4 + 0) * 64 + r] = v4.x * 0.125f;
            Qst[(c0 + u * 4 + 1) * 64 + r] = v4.y * 0.125f;
            Qst[(c0 + u * 4 + 2) * 64 + r] = v4.z * 0.125f;
            Qst[(c0 + u * 4 + 3) * 64 + r] = v4.w * 0.125f;
        }
    }
    float o[4][4] = {};
    float m_i[4], l_i[4];
    #pragma unroll
    for (int i = 0; i < 4; i++) { m_i[i] = -3.4e38f; l_i[i] = 0.f; }

    for (int kt = 0; kt <= qt; kt++) {
        __syncthreads();
        {
            int r = tid >> 2;
            int c0 = (tid & 3) << 4;
            const float* ks = g_kk + ((size_t)(b * SS + kt * 64 + r)) * HDIM + h * HD + c0;
            const float* vs = g_v + ((size_t)(b * SS + kt * 64 + r)) * HDIM + h * HD + c0;
            #pragma unroll
            for (int u = 0; u < 4; u++) {
                float4 v4 = *(const float4*)(ks + u * 4);
                Kst[(c0 + u * 4 + 0) * 64 + r] = v4.x;
                Kst[(c0 + u * 4 + 1) * 64 + r] = v4.y;
                Kst[(c0 + u * 4 + 2) * 64 + r] = v4.z;
                Kst[(c0 + u * 4 + 3) * 64 + r] = v4.w;
                *(float4*)&Vs[r * 64 + c0 + u * 4] = *(const float4*)(vs + u * 4);
            }
        }
        __syncthreads();
        float s[4][4] = {};
        #pragma unroll 4
        for (int d = 0; d < 64; d++) {
            float4 a4 = *(const float4*)&Qst[d * 64 + ty * 4];
            float4 b4 = *(const float4*)&Kst[d * 64 + tx * 4];
            float a[4] = {a4.x, a4.y, a4.z, a4.w};
            float bb[4] = {b4.x, b4.y, b4.z, b4.w};
            #pragma unroll
            for (int i = 0; i < 4; i++)
                #pragma unroll
                for (int j = 0; j < 4; j++)
                    s[i][j] = fmaf(a[i], bb[j], s[i][j]);
        }
        if (kt == qt) {
            #pragma unroll
            for (int i = 0; i < 4; i++)
                #pragma unroll
                for (int j = 0; j < 4; j++)
                    if (tx * 4 + j > ty * 4 + i) s[i][j] = -3.4e38f;
        }
        #pragma unroll
        for (int i = 0; i < 4; i++) {
            float mx = fmaxf(fmaxf(s[i][0], s[i][1]), fmaxf(s[i][2], s[i][3]));
            #pragma unroll
            for (int off = 8; off; off >>= 1)
                mx = fmaxf(mx, __shfl_xor_sync(0xffffffffu, mx, off));
            float mnew = fmaxf(m_i[i], mx);
            float alpha = __expf(m_i[i] - mnew);
            float rsum = 0.f;
            #pragma unroll
            for (int j = 0; j < 4; j++) {
                float p = __expf(s[i][j] - mnew);
                s[i][j] = p;
                rsum += p;
            }
            #pragma unroll
            for (int off = 8; off; off >>= 1)
                rsum += __shfl_xor_sync(0xffffffffu, rsum, off);
            l_i[i] = l_i[i] * alpha + rsum;
            m_i[i] = mnew;
            #pragma unroll
            for (int j = 0; j < 4; j++) {
                o[i][j] *= alpha;
                Pst[(tx * 4 + j) * 65 + ty * 4 + i] = s[i][j];
            }
        }
        __syncthreads();
        #pragma unroll 4
        for (int k = 0; k < 64; k++) {
            float a[4];
            #pragma unroll
            for (int i = 0; i < 4; i++) a[i] = Pst[k * 65 + ty * 4 + i];
            float4 b4 = *(const float4*)&Vs[k * 64 + tx * 4];
            float bb[4] = {b4.x, b4.y, b4.z, b4.w};
            #pragma unroll
            for (int i = 0; i < 4; i++)
                #pragma unroll
                for (int j = 0; j < 4; j++)
                    o[i][j] = fmaf(a[i], bb[j], o[i][j]);
        }
    }
    #pragma unroll
    for (int i = 0; i < 4; i++) {
        float inv = 1.0f / l_i[i];
        int q = qt * 64 + ty * 4 + i;
        float4 r = {o[i][0] * inv, o[i][1] * inv, o[i][2] * inv, o[i][3] * inv};
        *(float4*)(g_y + ((size_t)(b * SS + q)) * HDIM + h * HD + tx * 4) = r;
    }
}

// ---------------- router ---------------------------------------------------------
__global__ void zero_cnt_kernel() {
    if (threadIdx.x < NEXP) g_cnt[threadIdx.x] = 0;
}

__global__ void router_kernel(const float* __restrict__ Wr,
                              const float* __restrict__ bias) {
    int t = blockIdx.x * (blockDim.x >> 5) + (threadIdx.x >> 5);
    int lane = threadIdx.x & 31;
    if (t >= TT) return;
    const float* xr = g_xn2 + (size_t)t * HDIM;
    float acc[NEXP] = {};
    for (int h = lane; h < HDIM; h += 32) {
        float xv = xr[h];
        #pragma unroll
        for (int e = 0; e < NEXP; e++)
            acc[e] = fmaf(xv, Wr[h * NEXP + e], acc[e]);
    }
    #pragma unroll
    for (int e = 0; e < NEXP; e++)
        #pragma unroll
        for (int o = 16; o; o >>= 1)
            acc[e] += __shfl_xor_sync(0xffffffffu, acc[e], o);
    if (lane == 0) {
        float p[NEXP];
        #pragma unroll
        for (int e = 0; e < NEXP; e++)
            p[e] = 1.0f / (1.0f + expf(-(acc[e] + bias[e])));
        int i0 = 0;
        #pragma unroll
        for (int e = 1; e < NEXP; e++) if (p[e] > p[i0]) i0 = e;
        int i1 = (i0 == 0) ? 1 : 0;
        #pragma unroll
        for (int e = 0; e < NEXP; e++)
            if (e != i0 && p[e] > p[i1]) i1 = e;
        float ssum = p[i0] + p[i1];
        g_topidx[2 * t] = i0;
        g_topidx[2 * t + 1] = i1;
        g_topwt[2 * t] = p[i0] / ssum;
        g_topwt[2 * t + 1] = p[i1] / ssum;
        atomicAdd(&g_cnt[i0], 1);
        atomicAdd(&g_cnt[i1], 1);
    }
}

__global__ void prefix_kernel() {
    if (threadIdx.x == 0) {
        int off = 0;
        for (int e = 0; e < NEXP; e++) {
            g_poff[e] = off;
            off += (g_cnt[e] + 127) & ~127;   // pad segments to 128 rows
            g_fill[e] = 0;
        }
        g_poff[NEXP] = off;
    }
}

__global__ void scatter_kernel() {
    int t = blockIdx.x * blockDim.x + threadIdx.x;
    if (t >= TT) return;
    #pragma unroll
    for (int s = 0; s < 2; s++) {
        int e = g_topidx[2 * t + s];
        int pos = atomicAdd(&g_fill[e], 1);
        g_list[g_poff[e] + pos] = 2 * t + s;
    }
}

// ---------------- final combine: out = x1 + shared + w0*slot0 + w1*slot1 --------
__global__ void combine_kernel(float* __restrict__ out) {
    int i = blockIdx.x * blockDim.x + threadIdx.x;  // over TT*HDIM/4
    if (i >= TT * HDIM / 4) return;
    int c = i & (HDIM / 4 - 1);
    int t = i / (HDIM / 4);
    float w0 = g_topwt[2 * t], w1 = g_topwt[2 * t + 1];
    float4 a = ((const float4*)g_x1)[i];
    float4 sh = ((const float4*)g_sharedo)[i];
    float4 s0 = ((const float4*)g_slot)[(size_t)(2 * t) * (HDIM / 4) + c];
    float4 s1 = ((const float4*)g_slot)[(size_t)(2 * t + 1) * (HDIM / 4) + c];
    float4 r;
    r.x = a.x + sh.x + w0 * s0.x + w1 * s1.x;
    r.y = a.y + sh.y + w0 * s0.y + w1 * s1.y;
    r.z = a.z + sh.z + w0 * s0.z + w1 * s1.z;
    r.w = a.w + sh.w + w0 * s0.w + w1 * s1.w;
    ((float4*)out)[i] = r;
}

// ================================ host launcher =================================
static float* sym_f(const void* s) {
    void* p = nullptr;
    cudaGetSymbolAddress(&p, s);
    return (float*)p;
}

extern "C" void kernel_launch(void* const* d_in, const int* in_sizes, int n_in,
                              void* d_out, int out_size) {
    const float* x        = (const float*)d_in[0];
    const float* w_ln1    = (const float*)d_in[1];
    const float* w_ln2    = (const float*)d_in[2];
    const float* W_kvd    = (const float*)d_in[3];
    const float* W_qd     = (const float*)d_in[4];
    const float* W_ku     = (const float*)d_in[5];
    const float* W_qu     = (const float*)d_in[6];
    const float* W_vu     = (const float*)d_in[7];
    const float* W_ropeq  = (const float*)d_in[8];
    const float* W_ropek  = (const float*)d_in[9];
    const float* W_o      = (const float*)d_in[10];
    const float* Wg_s     = (const float*)d_in[11];
    const float* Wu_s     = (const float*)d_in[12];
    const float* Wd_s     = (const float*)d_in[13];
    const float* Wg_r     = (const float*)d_in[14];
    const float* Wu_r     = (const float*)d_in[15];
    const float* Wd_r     = (const float*)d_in[16];
    const float* W_router = (const float*)d_in[17];
    const float* r_bias   = (const float*)d_in[18];
    float* out = (float*)d_out;

    float* xn1    = sym_f(g_xn1);
    float* kvlat  = sym_f(g_kvlat);
    float* qlat   = sym_f(g_qlat);
    float* khalf  = sym_f(g_khalf);
    float* qhalf  = sym_f(g_qhalf);
    float* qropeb = sym_f(g_qropeb);
    float* kropeb = sym_f(g_kropeb);
    float* vbuf   = sym_f(g_v);
    float* ybuf   = sym_f(g_y);
    float* x1     = sym_f(g_x1);
    float* xn2    = sym_f(g_xn2);
    float* hmids  = sym_f(g_hmids);
    float* hmidu  = sym_f(g_hmidu);
    float* sharedo = sym_f(g_sharedo);
    float* hbuf   = sym_f(g_hbuf);
    float* hbufu  = sym_f(g_hbufu);
    float* slot   = sym_f(g_slot);

    static const int FLASH_SMEM = (4096 * 3 + 64 * 65) * 4;  // 65792 B
    cudaFuncSetAttribute(flash_kernel, cudaFuncAttributeMaxDynamicSharedMemorySize,
                         FLASH_SMEM);
    cudaFuncSetAttribute(mmt_core<0>, cudaFuncAttributeMaxDynamicSharedMemorySize,
                         MMT_SMEM);
    cudaFuncSetAttribute(mmt_core<1>, cudaFuncAttributeMaxDynamicSharedMemorySize,
                         MMT_SMEM);
    cudaFuncSetAttribute(mmt_core<2>, cudaFuncAttributeMaxDynamicSharedMemorySize,
                         MMT_SMEM);

    #define MMT(Ap, Bp, Dp, Cp, M, N, K) \
        mmt_core<0><<<dim3((N) / 128, (M) / 128), 256, MMT_SMEM>>>(Ap, Bp, Dp, Cp, M, N, K)

    // ---- MLA ----
    rmsnorm_kernel<<<TT, 256>>>(x, w_ln1, xn1);
    MMT(xn1, W_kvd, nullptr, kvlat, TT, LAT, HDIM);
    MMT(xn1, W_qd, nullptr, qlat, TT, LAT, HDIM);
    MMT(kvlat, W_ku, nullptr, khalf, TT, 512, LAT);
    MMT(qlat, W_qu, nullptr, qhalf, TT, 512, LAT);
    MMT(kvlat, W_vu, nullptr, vbuf, TT, HDIM, LAT);
    MMT(qlat, W_ropeq, nullptr, qropeb, TT, 512, LAT);
    MMT(xn1, W_ropek, nullptr, kropeb, TT, 512, HDIM);
    {
        int n = TT * NHEAD * HH;
        rope_concat_kernel<<<(n + 255) / 256, 256>>>();
    }
    flash_kernel<<<dim3(SS / 64, NHEAD, BB), 256, FLASH_SMEM>>>();
    // x1 = x + y @ W_o
    MMT(ybuf, W_o, x, x1, TT, HDIM, HDIM);

    // ---- MoE ----
    rmsnorm_kernel<<<TT, 256>>>(x1, w_ln2, xn2);
    zero_cnt_kernel<<<1, 32>>>();
    router_kernel<<<TT / 4, 128>>>(W_router, r_bias);
    prefix_kernel<<<1, 32>>>();
    scatter_kernel<<<(TT + 255) / 256, 256>>>();
    // shared expert: two tf32 GEMMs + silu-mul + down GEMM
    MMT(xn2, Wg_s, nullptr, hmids, TT, IDIM, HDIM);
    MMT(xn2, Wu_s, nullptr, hmidu, TT, IDIM, HDIM);
    silumul_kernel<<<(TT * IDIM / 4 + 255) / 256, 256>>>(hmids, hmidu, TT * IDIM / 4);
    MMT(hmids, Wd_s, nullptr, sharedo, TT, HDIM, IDIM);
    // routed experts (sparse, padded 128-row segments)
    mmt_core<1><<<dim3(IDIM / 128, HBUF_ROWS / 128), 256, MMT_SMEM>>>(
        xn2, Wg_r, nullptr, hbuf, HBUF_ROWS, IDIM, HDIM);
    mmt_core<1><<<dim3(IDIM / 128, HBUF_ROWS / 128), 256, MMT_SMEM>>>(
        xn2, Wu_r, nullptr, hbufu, HBUF_ROWS, IDIM, HDIM);
    silumul_kernel<<<(HBUF_ROWS * IDIM / 4 + 255) / 256, 256>>>(
        hbuf, hbufu, HBUF_ROWS * IDIM / 4);
    mmt_core<2><<<dim3(HDIM / 128, HBUF_ROWS / 128), 256, MMT_SMEM>>>(
        hbuf, Wd_r, nullptr, slot, HBUF_ROWS, HDIM, IDIM);
    // out = x1 + shared + weighted routed
    combine_kernel<<<(TT * HDIM / 4 + 255) / 256, 256>>>(out);
}

// round 8
// speedup vs baseline: 2.3359x; 1.1225x over previous
#include <cuda_runtime.h>
#include <math.h>
#include <stdint.h>

// Problem constants
#define HDIM 1024
#define NHEAD 16
#define HD 64
#define HH 32
#define LAT 256
#define IDIM 1024
#define NEXP 7
#define BB 4
#define SS 1024
#define TT 4096            // BB*SS tokens
#define HBUF_ROWS 9216     // padded routed rows (2*TT + 7*127, rounded to 128)

// TF32 MMA pipeline geometry: BM=BN=128, BK=16, 4 stages
#define ASTR 20                    // A stage: 128 rows x 16 k, stride 20 (80B, 16B-mult)
#define BSTR 136                   // B stage: 16 k x 128 n, stride 136 (544B, 16B-mult)
#define A_ST (128 * ASTR)          // 2560 floats
#define B_ST (16 * BSTR)           // 2176 floats
#define STAGE_F (A_ST + B_ST)      // 4736 floats
#define NSTAGE 4
#define MMT_SMEM (NSTAGE * STAGE_F * 4)   // 75776 bytes

// Flash TC geometry
#define FD 68                      // padded row stride for 64-wide tiles
#define FLASH_SMEM_TC (3 * 64 * FD * 4)   // Kst + Vs + Ps = 52224 bytes

// ---------------- scratch (device globals; no allocation allowed) ----------------
__device__ float g_xn1[TT * HDIM];
__device__ float g_kvlat[TT * LAT];
__device__ float g_qlat[TT * LAT];
__device__ float g_khalf[TT * NHEAD * HH];
__device__ float g_qhalf[TT * NHEAD * HH];
__device__ float g_qropeb[TT * NHEAD * HH];
__device__ float g_kropeb[TT * NHEAD * HH];
__device__ float g_v[TT * HDIM];
__device__ float g_kk[TT * HDIM];
__device__ float g_qq[TT * HDIM];
__device__ float g_y[TT * HDIM];
__device__ float g_x1[TT * HDIM];
__device__ float g_xn2[TT * HDIM];
__device__ float g_hmids[TT * IDIM];
__device__ float g_hmidu[TT * IDIM];
__device__ float g_sharedo[TT * HDIM];
__device__ float g_hbuf[HBUF_ROWS * IDIM];
__device__ float g_hbufu[HBUF_ROWS * IDIM];
__device__ float g_slot[TT * 2 * HDIM];
__device__ int   g_topidx[TT * 2];
__device__ float g_topwt[TT * 2];
__device__ int   g_cnt[NEXP];
__device__ int   g_poff[NEXP + 1];
__device__ int   g_fill[NEXP];
__device__ int   g_list[HBUF_ROWS];

__device__ __forceinline__ float silu_f(float g) {
    return g / (1.0f + __expf(-g));
}

__device__ __forceinline__ void cpa16(uint32_t dst, const void* src) {
    asm volatile("cp.async.ca.shared.global [%0], [%1], 16;\n" :: "r"(dst), "l"(src));
}
__device__ __forceinline__ void cpa_commit() {
    asm volatile("cp.async.commit_group;\n");
}
template <int N>
__device__ __forceinline__ void cpa_wait() {
    asm volatile("cp.async.wait_group %0;\n" :: "n"(N));
}

__device__ __forceinline__ void mma8(float* d, const unsigned* a, unsigned b0, unsigned b1) {
    asm volatile(
        "mma.sync.aligned.m16n8k8.row.col.f32.tf32.tf32.f32 "
        "{%0,%1,%2,%3}, {%4,%5,%6,%7}, {%8,%9}, {%0,%1,%2,%3};\n"
        : "+f"(d[0]), "+f"(d[1]), "+f"(d[2]), "+f"(d[3])
        : "r"(a[0]), "r"(a[1]), "r"(a[2]), "r"(a[3]), "r"(b0), "r"(b1));
}

// ================= TF32 tensor-core GEMM: C = A[M,K] @ B[K,N] (+Dres) ===========
// MODE 0: plain (optional Dres residual add)
// MODE 1: MoE gather — A rows gathered from token list, B expert-selected
// MODE 2: MoE scatter — A rows direct (hbuf), B expert-selected, C scattered
// BM=BN=128, BK=16, 4-stage cp.async pipeline, 256 threads (8 warps, 32x64 each).
template <int MODE>
__global__ void __launch_bounds__(256, 2) mmt_core(
    const float* __restrict__ A, const float* __restrict__ B,
    const float* __restrict__ Dres, float* __restrict__ C,
    int M, int N, int K) {
    extern __shared__ float smf[];
    __shared__ int spoff[NEXP + 1];
    __shared__ int scnt[NEXP];
    int tid = threadIdx.x, lane = tid & 31, wid = tid >> 5;
    int m0 = blockIdx.y * 128, n0 = blockIdx.x * 128;
    int e = 0;
    if (MODE != 0) {
        if (tid <= NEXP) spoff[tid] = g_poff[tid];
        if (tid < NEXP) scnt[tid] = g_cnt[tid];
        __syncthreads();
        if (m0 >= spoff[NEXP]) return;
        while (m0 >= spoff[e + 1]) e++;
        B += (size_t)e * K * N;
    }
    int wm = (wid & 3) * 32, wn = (wid >> 2) * 64;
    int arow = tid >> 1, ahalf = (tid & 1) * 8;
    int brow = tid >> 4, bcol = (tid & 15) * 8;
    const float* asrc;
    if (MODE == 1) {
        int grow = m0 + arow;
        int tok = ((grow - spoff[e]) < scnt[e]) ? (g_list[grow] >> 1) : 0;
        asrc = A + (size_t)tok * K + ahalf;
    } else {
        asrc = A + (size_t)(m0 + arow) * K + ahalf;
    }
    const float* bsrc = B + (size_t)brow * N + n0 + bcol;

    uint32_t smem_u = (uint32_t)__cvta_generic_to_shared(smf);
    uint32_t a_dst0 = smem_u + (arow * ASTR + ahalf) * 4;
    uint32_t b_dst0 = smem_u + (A_ST + brow * BSTR + bcol) * 4;

    float acc[2][8][4];
    #pragma unroll
    for (int mi = 0; mi < 2; mi++)
        #pragma unroll
        for (int nj = 0; nj < 8; nj++)
            #pragma unroll
            for (int q = 0; q < 4; q++) acc[mi][nj][q] = 0.f;

    int kiters = K >> 4;
    #pragma unroll
    for (int s = 0; s < NSTAGE - 1; s++) {
        int k0 = s * 16;
        uint32_t so = s * (STAGE_F * 4);
        cpa16(a_dst0 + so, asrc + k0);
        cpa16(a_dst0 + so + 16, asrc + k0 + 4);
        cpa16(b_dst0 + so, bsrc + (size_t)k0 * N);
        cpa16(b_dst0 + so + 16, bsrc + (size_t)k0 * N + 4);
        cpa_commit();
    }

    int r = lane >> 2, c = lane & 3;
    for (int it = 0; it < kiters; it++) {
        cpa_wait<NSTAGE - 2>();
        __syncthreads();
        int nk = it + NSTAGE - 1;
        if (nk < kiters) {
            int s = nk & (NSTAGE - 1);
            int k0 = nk * 16;
            uint32_t so = s * (STAGE_F * 4);
            cpa16(a_dst0 + so, asrc + k0);
            cpa16(a_dst0 + so + 16, asrc + k0 + 4);
            cpa16(b_dst0 + so, bsrc + (size_t)k0 * N);
            cpa16(b_dst0 + so + 16, bsrc + (size_t)k0 * N + 4);
        }
        cpa_commit();

        const float* Asb = smf + (it & (NSTAGE - 1)) * STAGE_F;
        const float* Bsb = Asb + A_ST;
        #pragma unroll
        for (int ks = 0; ks < 2; ks++) {
            int kk = ks * 8;
            unsigned af[2][4];
            #pragma unroll
            for (int mi = 0; mi < 2; mi++) {
                const float* ab = Asb + (wm + mi * 16 + r) * ASTR + kk + c;
                af[mi][0] = __float_as_uint(ab[0]);
                af[mi][1] = __float_as_uint(ab[8 * ASTR]);
                af[mi][2] = __float_as_uint(ab[4]);
                af[mi][3] = __float_as_uint(ab[8 * ASTR + 4]);
            }
            #pragma unroll
            for (int nj = 0; nj < 8; nj++) {
                const float* bb = Bsb + (kk + c) * BSTR + wn + nj * 8 + r;
                unsigned b0 = __float_as_uint(bb[0]);
                unsigned b1 = __float_as_uint(bb[4 * BSTR]);
                mma8(acc[0][nj], af[0], b0, b1);
                mma8(acc[1][nj], af[1], b0, b1);
            }
        }
    }
    #pragma unroll
    for (int mi = 0; mi < 2; mi++) {
        #pragma unroll
        for (int h = 0; h < 2; h++) {
            int m = m0 + wm + mi * 16 + r + h * 8;
            if (MODE == 2) {
                if ((m - spoff[e]) >= scnt[e]) continue;
                int enc = g_list[m];  // 2*token + slot
                float* crow = C + (size_t)enc * N + n0 + wn;
                #pragma unroll
                for (int nj = 0; nj < 8; nj++) {
                    float2 v = {acc[mi][nj][h * 2], acc[mi][nj][h * 2 + 1]};
                    *(float2*)(crow + nj * 8 + c * 2) = v;
                }
            } else {
                float* crow = C + (size_t)m * N + n0 + wn;
                const float* drow = Dres ? (Dres + (size_t)m * N + n0 + wn) : nullptr;
                #pragma unroll
                for (int nj = 0; nj < 8; nj++) {
                    float2 v = {acc[mi][nj][h * 2], acc[mi][nj][h * 2 + 1]};
                    if (MODE == 0 && drow) {
                        float2 d = *(const float2*)(drow + nj * 8 + c * 2);
                        v.x += d.x; v.y += d.y;
                    }
                    *(float2*)(crow + nj * 8 + c * 2) = v;
                }
            }
        }
    }
}

// ---------------- elementwise: g = silu(g) * u ----------------------------------
__global__ void silumul_kernel(float* __restrict__ g, const float* __restrict__ u,
                               int n4) {
    int i = blockIdx.x * blockDim.x + threadIdx.x;
    if (i >= n4) return;
    float4 gv = ((float4*)g)[i];
    float4 uv = ((const float4*)u)[i];
    gv.x = silu_f(gv.x) * uv.x;
    gv.y = silu_f(gv.y) * uv.y;
    gv.z = silu_f(gv.z) * uv.z;
    gv.w = silu_f(gv.w) * uv.w;
    ((float4*)g)[i] = gv;
}

// ---------------- rmsnorm -------------------------------------------------------
__global__ void rmsnorm_kernel(const float* __restrict__ x,
                               const float* __restrict__ w,
                               float* __restrict__ out) {
    int t = blockIdx.x;
    const float* xr = x + (size_t)t * HDIM;
    float ss = 0.f;
    for (int h = threadIdx.x; h < HDIM; h += blockDim.x) {
        float v = xr[h];
        ss += v * v;
    }
    __shared__ float red[32];
    #pragma unroll
    for (int o = 16; o; o >>= 1) ss += __shfl_xor_sync(0xffffffffu, ss, o);
    if ((threadIdx.x & 31) == 0) red[threadIdx.x >> 5] = ss;
    __syncthreads();
    if (threadIdx.x < 32) {
        float v = (threadIdx.x < (blockDim.x >> 5)) ? red[threadIdx.x] : 0.f;
        #pragma unroll
        for (int o = 16; o; o >>= 1) v += __shfl_xor_sync(0xffffffffu, v, o);
        if (threadIdx.x == 0) red[0] = v;
    }
    __syncthreads();
    float inv = 1.0f / (sqrtf(red[0] * (1.0f / HDIM)) + 1e-5f);
    float* orow = out + (size_t)t * HDIM;
    for (int h = threadIdx.x; h < HDIM; h += blockDim.x)
        orow[h] = xr[h] * inv * w[h];
}

// ---------------- RoPE + concat into qq/kk [T, NH, 64] --------------------------
__global__ void rope_concat_kernel() {
    int i = blockIdx.x * blockDim.x + threadIdx.x;  // over TT*NHEAD*HH
    if (i >= TT * NHEAD * HH) return;
    int d = i & 31;
    int h = (i >> 5) & 15;
    int t = i >> 9;
    int s = t & (SS - 1);
    int j = d & 15;
    float invf = expf(-((float)j / 16.0f) * 9.210340371976184f);  // ln(10000)
    float ang = (float)s * invf;
    float c = cosf(ang), sn = sinf(ang);
    int o = t * HDIM + h * HD + d;
    float kr = g_kropeb[i];
    float krot = (d < 16) ? -g_kropeb[i + 16] : g_kropeb[i - 16];
    g_kk[o] = g_khalf[i];
    g_kk[o + HH] = kr * c + krot * sn;
    float qr = g_qropeb[i];
    float qrot = (d < 16) ? -g_qropeb[i + 16] : g_qropeb[i - 16];
    g_qq[o] = g_qhalf[i];
    g_qq[o + HH] = qr * c + qrot * sn;
}

// ============ flash attention on TF32 tensor cores: causal, 64x64, d=64 =========
// 128 threads / 4 warps; warp owns 16 q-rows. Q kept in registers as A-fragments.
// S = Q K^T via m16n8k8; online softmax on d-fragments; P via smem (warp-private
// rows, __syncwarp only); O += P V via m16n8k8.
__global__ void __launch_bounds__(128, 2) flash_kernel() {
    extern __shared__ float sm[];
    float* Kst = sm;                 // [d][kcol]   64 x FD
    float* Vs  = sm + 64 * FD;       // [kcol][d]   64 x FD
    float* Ps  = sm + 2 * 64 * FD;   // [q][kcol]   64 x FD
    int qt = blockIdx.x, h = blockIdx.y, b = blockIdx.z;
    int tid = threadIdx.x, lane = tid & 31, wq = tid >> 5;
    int gr = lane >> 2, gc = lane & 3;

    // Q fragments (scaled by 1/8 = 1/sqrt(64))
    unsigned aq[8][4];
    {
        const float* q0 = g_qq + ((size_t)(b * SS + qt * 64 + wq * 16 + gr)) * HDIM + h * HD;
        const float* q8 = q0 + 8 * HDIM;
        #pragma unroll
        for (int ks = 0; ks < 8; ks++) {
            int kk = ks * 8;
            aq[ks][0] = __float_as_uint(q0[kk + gc] * 0.125f);
            aq[ks][1] = __float_as_uint(q8[kk + gc] * 0.125f);
            aq[ks][2] = __float_as_uint(q0[kk + gc + 4] * 0.125f);
            aq[ks][3] = __float_as_uint(q8[kk + gc + 4] * 0.125f);
        }
    }
    float m_[2] = {-3.4e38f, -3.4e38f}, l_[2] = {0.f, 0.f};
    float o[8][4];
    #pragma unroll
    for (int nj = 0; nj < 8; nj++)
        #pragma unroll
        for (int q = 0; q < 4; q++) o[nj][q] = 0.f;

    for (int kt = 0; kt <= qt; kt++) {
        __syncthreads();   // protect Kst/Vs from previous iteration's readers
        {
            int r = tid >> 1;
            int c0 = (tid & 1) * 32;
            const float* ksrc = g_kk + ((size_t)(b * SS + kt * 64 + r)) * HDIM + h * HD + c0;
            const float* vsrc = g_v + ((size_t)(b * SS + kt * 64 + r)) * HDIM + h * HD + c0;
            #pragma unroll
            for (int u = 0; u < 8; u++) {
                float4 kv = *(const float4*)(ksrc + u * 4);
                Kst[(c0 + u * 4 + 0) * FD + r] = kv.x;
                Kst[(c0 + u * 4 + 1) * FD + r] = kv.y;
                Kst[(c0 + u * 4 + 2) * FD + r] = kv.z;
                Kst[(c0 + u * 4 + 3) * FD + r] = kv.w;
                *(float4*)&Vs[r * FD + c0 + u * 4] = *(const float4*)(vsrc + u * 4);
            }
        }
        __syncthreads();

        // S = Q K^T  (warp: 16 q-rows x 64 k-cols)
        float s[8][4] = {};
        #pragma unroll
        for (int ks = 0; ks < 8; ks++) {
            int kk = ks * 8;
            #pragma unroll
            for (int nj = 0; nj < 8; nj++) {
                const float* bb = &Kst[(kk + gc) * FD + nj * 8 + gr];
                mma8(s[nj], aq[ks], __float_as_uint(bb[0]), __float_as_uint(bb[4 * FD]));
            }
        }
        if (kt == qt) {
            int row0 = wq * 16 + gr;
            #pragma unroll
            for (int nj = 0; nj < 8; nj++) {
                int col0 = nj * 8 + 2 * gc;
                if (col0 > row0) s[nj][0] = -3.4e38f;
                if (col0 + 1 > row0) s[nj][1] = -3.4e38f;
                if (col0 > row0 + 8) s[nj][2] = -3.4e38f;
                if (col0 + 1 > row0 + 8) s[nj][3] = -3.4e38f;
            }
        }
        // online softmax: 2 rows per thread (gr, gr+8); quad lanes share a row
        #pragma unroll
        for (int q2 = 0; q2 < 2; q2++) {
            float mx = -3.4e38f;
            #pragma unroll
            for (int nj = 0; nj < 8; nj++)
                mx = fmaxf(mx, fmaxf(s[nj][q2 * 2], s[nj][q2 * 2 + 1]));
            mx = fmaxf(mx, __shfl_xor_sync(0xffffffffu, mx, 1));
            mx = fmaxf(mx, __shfl_xor_sync(0xffffffffu, mx, 2));
            float mnew = fmaxf(m_[q2], mx);
            float alpha = __expf(m_[q2] - mnew);
            float sum = 0.f;
            #pragma unroll
            for (int nj = 0; nj < 8; nj++) {
                float p0 = __expf(s[nj][q2 * 2] - mnew);
                float p1 = __expf(s[nj][q2 * 2 + 1] - mnew);
                s[nj][q2 * 2] = p0;
                s[nj][q2 * 2 + 1] = p1;
                sum += p0 + p1;
            }
            sum += __shfl_xor_sync(0xffffffffu, sum, 1);
            sum += __shfl_xor_sync(0xffffffffu, sum, 2);
            l_[q2] = l_[q2] * alpha + sum;
            m_[q2] = mnew;
            #pragma unroll
            for (int nj = 0; nj < 8; nj++) {
                o[nj][q2 * 2] *= alpha;
                o[nj][q2 * 2 + 1] *= alpha;
            }
        }
        // P to smem (rows are warp-private; only this warp reads them back)
        {
            int r0 = wq * 16 + gr;
            #pragma unroll
            for (int nj = 0; nj < 8; nj++) {
                *(float2*)&Ps[r0 * FD + nj * 8 + 2 * gc] = make_float2(s[nj][0], s[nj][1]);
                *(float2*)&Ps[(r0 + 8) * FD + nj * 8 + 2 * gc] = make_float2(s[nj][2], s[nj][3]);
            }
        }
        __syncwarp();
        // O += P V
        #pragma unroll
        for (int ks = 0; ks < 8; ks++) {
            int kk = ks * 8;
            int r0 = wq * 16 + gr;
            unsigned ap[4];
            ap[0] = __float_as_uint(Ps[r0 * FD + kk + gc]);
            ap[1] = __float_as_uint(Ps[(r0 + 8) * FD + kk + gc]);
            ap[2] = __float_as_uint(Ps[r0 * FD + kk + gc + 4]);
            ap[3] = __float_as_uint(Ps[(r0 + 8) * FD + kk + gc + 4]);
            #pragma unroll
            for (int nj = 0; nj < 8; nj++) {
                const float* bb = &Vs[(kk + gc) * FD + nj * 8 + gr];
                mma8(o[nj], ap, __float_as_uint(bb[0]), __float_as_uint(bb[4 * FD]));
            }
        }
        __syncwarp();  // Ps reads done before next iteration's overwrite
    }
    // epilogue: normalize and store
    float inv0 = 1.0f / l_[0], inv1 = 1.0f / l_[1];
    int row0 = b * SS + qt * 64 + wq * 16 + gr;
    float* out0 = g_y + (size_t)row0 * HDIM + h * HD;
    float* out8 = out0 + 8 * HDIM;
    #pragma unroll
    for (int nj = 0; nj < 8; nj++) {
        *(float2*)&out0[nj * 8 + 2 * gc] = make_float2(o[nj][0] * inv0, o[nj][1] * inv0);
        *(float2*)&out8[nj * 8 + 2 * gc] = make_float2(o[nj][2] * inv1, o[nj][3] * inv1);
    }
}

// ---------------- router ---------------------------------------------------------
__global__ void zero_cnt_kernel() {
    if (threadIdx.x < NEXP) g_cnt[threadIdx.x] = 0;
}

__global__ void router_kernel(const float* __restrict__ Wr,
                              const float* __restrict__ bias) {
    int t = blockIdx.x * (blockDim.x >> 5) + (threadIdx.x >> 5);
    int lane = threadIdx.x & 31;
    if (t >= TT) return;
    const float* xr = g_xn2 + (size_t)t * HDIM;
    float acc[NEXP] = {};
    for (int h = lane; h < HDIM; h += 32) {
        float xv = xr[h];
        #pragma unroll
        for (int e = 0; e < NEXP; e++)
            acc[e] = fmaf(xv, Wr[h * NEXP + e], acc[e]);
    }
    #pragma unroll
    for (int e = 0; e < NEXP; e++)
        #pragma unroll
        for (int o = 16; o; o >>= 1)
            acc[e] += __shfl_xor_sync(0xffffffffu, acc[e], o);
    if (lane == 0) {
        float p[NEXP];
        #pragma unroll
        for (int e = 0; e < NEXP; e++)
            p[e] = 1.0f / (1.0f + expf(-(acc[e] + bias[e])));
        int i0 = 0;
        #pragma unroll
        for (int e = 1; e < NEXP; e++) if (p[e] > p[i0]) i0 = e;
        int i1 = (i0 == 0) ? 1 : 0;
        #pragma unroll
        for (int e = 0; e < NEXP; e++)
            if (e != i0 && p[e] > p[i1]) i1 = e;
        float ssum = p[i0] + p[i1];
        g_topidx[2 * t] = i0;
        g_topidx[2 * t + 1] = i1;
        g_topwt[2 * t] = p[i0] / ssum;
        g_topwt[2 * t + 1] = p[i1] / ssum;
        atomicAdd(&g_cnt[i0], 1);
        atomicAdd(&g_cnt[i1], 1);
    }
}

__global__ void prefix_kernel() {
    if (threadIdx.x == 0) {
        int off = 0;
        for (int e = 0; e < NEXP; e++) {
            g_poff[e] = off;
            off += (g_cnt[e] + 127) & ~127;   // pad segments to 128 rows
            g_fill[e] = 0;
        }
        g_poff[NEXP] = off;
    }
}

__global__ void scatter_kernel() {
    int t = blockIdx.x * blockDim.x + threadIdx.x;
    if (t >= TT) return;
    #pragma unroll
    for (int s = 0; s < 2; s++) {
        int e = g_topidx[2 * t + s];
        int pos = atomicAdd(&g_fill[e], 1);
        g_list[g_poff[e] + pos] = 2 * t + s;
    }
}

// ---------------- final combine: out = x1 + shared + w0*slot0 + w1*slot1 --------
__global__ void combine_kernel(float* __restrict__ out) {
    int i = blockIdx.x * blockDim.x + threadIdx.x;  // over TT*HDIM/4
    if (i >= TT * HDIM / 4) return;
    int c = i & (HDIM / 4 - 1);
    int t = i / (HDIM / 4);
    float w0 = g_topwt[2 * t], w1 = g_topwt[2 * t + 1];
    float4 a = ((const float4*)g_x1)[i];
    float4 sh = ((const float4*)g_sharedo)[i];
    float4 s0 = ((const float4*)g_slot)[(size_t)(2 * t) * (HDIM / 4) + c];
    float4 s1 = ((const float4*)g_slot)[(size_t)(2 * t + 1) * (HDIM / 4) + c];
    float4 r;
    r.x = a.x + sh.x + w0 * s0.x + w1 * s1.x;
    r.y = a.y + sh.y + w0 * s0.y + w1 * s1.y;
    r.z = a.z + sh.z + w0 * s0.z + w1 * s1.z;
    r.w = a.w + sh.w + w0 * s0.w + w1 * s1.w;
    ((float4*)out)[i] = r;
}

// ================================ host launcher =================================
static float* sym_f(const void* s) {
    void* p = nullptr;
    cudaGetSymbolAddress(&p, s);
    return (float*)p;
}

extern "C" void kernel_launch(void* const* d_in, const int* in_sizes, int n_in,
                              void* d_out, int out_size) {
    const float* x        = (const float*)d_in[0];
    const float* w_ln1    = (const float*)d_in[1];
    const float* w_ln2    = (const float*)d_in[2];
    const float* W_kvd    = (const float*)d_in[3];
    const float* W_qd     = (const float*)d_in[4];
    const float* W_ku     = (const float*)d_in[5];
    const float* W_qu     = (const float*)d_in[6];
    const float* W_vu     = (const float*)d_in[7];
    const float* W_ropeq  = (const float*)d_in[8];
    const float* W_ropek  = (const float*)d_in[9];
    const float* W_o      = (const float*)d_in[10];
    const float* Wg_s     = (const float*)d_in[11];
    const float* Wu_s     = (const float*)d_in[12];
    const float* Wd_s     = (const float*)d_in[13];
    const float* Wg_r     = (const float*)d_in[14];
    const float* Wu_r     = (const float*)d_in[15];
    const float* Wd_r     = (const float*)d_in[16];
    const float* W_router = (const float*)d_in[17];
    const float* r_bias   = (const float*)d_in[18];
    float* out = (float*)d_out;

    float* xn1    = sym_f(g_xn1);
    float* kvlat  = sym_f(g_kvlat);
    float* qlat   = sym_f(g_qlat);
    float* khalf  = sym_f(g_khalf);
    float* qhalf  = sym_f(g_qhalf);
    float* qropeb = sym_f(g_qropeb);
    float* kropeb = sym_f(g_kropeb);
    float* vbuf   = sym_f(g_v);
    float* ybuf   = sym_f(g_y);
    float* x1     = sym_f(g_x1);
    float* xn2    = sym_f(g_xn2);
    float* hmids  = sym_f(g_hmids);
    float* hmidu  = sym_f(g_hmidu);
    float* sharedo = sym_f(g_sharedo);
    float* hbuf   = sym_f(g_hbuf);
    float* hbufu  = sym_f(g_hbufu);
    float* slot   = sym_f(g_slot);

    cudaFuncSetAttribute(flash_kernel, cudaFuncAttributeMaxDynamicSharedMemorySize,
                         FLASH_SMEM_TC);
    cudaFuncSetAttribute(mmt_core<0>, cudaFuncAttributeMaxDynamicSharedMemorySize,
                         MMT_SMEM);
    cudaFuncSetAttribute(mmt_core<1>, cudaFuncAttributeMaxDynamicSharedMemorySize,
                         MMT_SMEM);
    cudaFuncSetAttribute(mmt_core<2>, cudaFuncAttributeMaxDynamicSharedMemorySize,
                         MMT_SMEM);

    #define MMT(Ap, Bp, Dp, Cp, M, N, K) \
        mmt_core<0><<<dim3((N) / 128, (M) / 128), 256, MMT_SMEM>>>(Ap, Bp, Dp, Cp, M, N, K)

    // ---- MLA ----
    rmsnorm_kernel<<<TT, 256>>>(x, w_ln1, xn1);
    MMT(xn1, W_kvd, nullptr, kvlat, TT, LAT, HDIM);
    MMT(xn1, W_qd, nullptr, qlat, TT, LAT, HDIM);
    MMT(kvlat, W_ku, nullptr, khalf, TT, 512, LAT);
    MMT(qlat, W_qu, nullptr, qhalf, TT, 512, LAT);
    MMT(kvlat, W_vu, nullptr, vbuf, TT, HDIM, LAT);
    MMT(qlat, W_ropeq, nullptr, qropeb, TT, 512, LAT);
    MMT(xn1, W_ropek, nullptr, kropeb, TT, 512, HDIM);
    {
        int n = TT * NHEAD * HH;
        rope_concat_kernel<<<(n + 255) / 256, 256>>>();
    }
    flash_kernel<<<dim3(SS / 64, NHEAD, BB), 128, FLASH_SMEM_TC>>>();
    // x1 = x + y @ W_o
    MMT(ybuf, W_o, x, x1, TT, HDIM, HDIM);

    // ---- MoE ----
    rmsnorm_kernel<<<TT, 256>>>(x1, w_ln2, xn2);
    zero_cnt_kernel<<<1, 32>>>();
    router_kernel<<<TT / 4, 128>>>(W_router, r_bias);
    prefix_kernel<<<1, 32>>>();
    scatter_kernel<<<(TT + 255) / 256, 256>>>();
    // shared expert: two tf32 GEMMs + silu-mul + down GEMM
    MMT(xn2, Wg_s, nullptr, hmids, TT, IDIM, HDIM);
    MMT(xn2, Wu_s, nullptr, hmidu, TT, IDIM, HDIM);
    silumul_kernel<<<(TT * IDIM / 4 + 255) / 256, 256>>>(hmids, hmidu, TT * IDIM / 4);
    MMT(hmids, Wd_s, nullptr, sharedo, TT, HDIM, IDIM);
    // routed experts (sparse, padded 128-row segments)
    mmt_core<1><<<dim3(IDIM / 128, HBUF_ROWS / 128), 256, MMT_SMEM>>>(
        xn2, Wg_r, nullptr, hbuf, HBUF_ROWS, IDIM, HDIM);
    mmt_core<1><<<dim3(IDIM / 128, HBUF_ROWS / 128), 256, MMT_SMEM>>>(
        xn2, Wu_r, nullptr, hbufu, HBUF_ROWS, IDIM, HDIM);
    silumul_kernel<<<(HBUF_ROWS * IDIM / 4 + 255) / 256, 256>>>(
        hbuf, hbufu, HBUF_ROWS * IDIM / 4);
    mmt_core<2><<<dim3(HDIM / 128, HBUF_ROWS / 128), 256, MMT_SMEM>>>(
        hbuf, Wd_r, nullptr, slot, HBUF_ROWS, HDIM, IDIM);
    // out = x1 + shared + weighted routed
    combine_kernel<<<(TT * HDIM / 4 + 255) / 256, 256>>>(out);
}

// round 10
// speedup vs baseline: 2.4345x; 1.0422x over previous
#include <cuda_runtime.h>
#include <math.h>
#include <stdint.h>

// Problem constants
#define HDIM 1024
#define NHEAD 16
#define HD 64
#define HH 32
#define LAT 256
#define IDIM 1024
#define NEXP 7
#define BB 4
#define SS 1024
#define TT 4096            // BB*SS tokens
#define HBUF_ROWS 9216     // padded routed rows (2*TT + 7*127, rounded to 128)

// TF32 MMA pipeline geometry: BM=BN=128, BK=16, 4 stages
#define ASTR 20                    // A stage: 128 rows x 16 k, stride 20 (80B, 16B-mult)
#define BSTR 136                   // B stage: 16 k x 128 n, stride 136 (544B, 16B-mult)
#define A_ST (128 * ASTR)          // 2560 floats
#define B_ST (16 * BSTR)           // 2176 floats
#define STAGE_F (A_ST + B_ST)      // 4736 floats
#define NSTAGE 4
#define MMT_SMEM (NSTAGE * STAGE_F * 4)   // 75776 bytes

// Flash TC geometry
#define FD 68
#define FLASH_SMEM_TC (3 * 64 * FD * 4)   // 52224 bytes

// ---------------- scratch (device globals; no allocation allowed) ----------------
__device__ float g_xn1[TT * HDIM];
__device__ float g_kvlat[TT * LAT];
__device__ float g_qlat[TT * LAT];
__device__ float g_khalf[TT * NHEAD * HH];
__device__ float g_qhalf[TT * NHEAD * HH];
__device__ float g_qropeb[TT * NHEAD * HH];
__device__ float g_kropeb[TT * NHEAD * HH];
__device__ float g_v[TT * HDIM];
__device__ float g_kk[TT * HDIM];
__device__ float g_qq[TT * HDIM];
__device__ float g_y[TT * HDIM];
__device__ float g_x1[TT * HDIM];
__device__ float g_xn2[TT * HDIM];
__device__ float g_hmids[TT * IDIM];
__device__ float g_hmidu[TT * IDIM];
__device__ float g_sharedo[TT * HDIM];
__device__ float g_hbuf[HBUF_ROWS * IDIM];
__device__ float g_hbufu[HBUF_ROWS * IDIM];
__device__ float g_slot[TT * 2 * HDIM];
__device__ int   g_topidx[TT * 2];
__device__ float g_topwt[TT * 2];
__device__ int   g_cnt[NEXP];
__device__ int   g_poff[NEXP + 1];
__device__ int   g_fill[NEXP];
__device__ int   g_list[HBUF_ROWS];

__device__ __forceinline__ float silu_f(float g) {
    return g / (1.0f + __expf(-g));
}

__device__ __forceinline__ void cpa16(uint32_t dst, const void* src) {
    asm volatile("cp.async.ca.shared.global [%0], [%1], 16;\n" :: "r"(dst), "l"(src));
}
__device__ __forceinline__ void cpa_commit() {
    asm volatile("cp.async.commit_group;\n");
}
template <int N>
__device__ __forceinline__ void cpa_wait() {
    asm volatile("cp.async.wait_group %0;\n" :: "n"(N));
}

__device__ __forceinline__ void mma8(float* d, const unsigned* a, unsigned b0, unsigned b1) {
    asm volatile(
        "mma.sync.aligned.m16n8k8.row.col.f32.tf32.tf32.f32 "
        "{%0,%1,%2,%3}, {%4,%5,%6,%7}, {%8,%9}, {%0,%1,%2,%3};\n"
        : "+f"(d[0]), "+f"(d[1]), "+f"(d[2]), "+f"(d[3])
        : "r"(a[0]), "r"(a[1]), "r"(a[2]), "r"(a[3]), "r"(b0), "r"(b1));
}

// Batched pointer set: one GEMM problem per blockIdx.z (same M,N,K per batch).
struct GB {
    const float* A[3];
    const float* B[3];
    const float* D[3];
    float* C[3];
};

// ================= TF32 tensor-core GEMM: C = A[M,K] @ B[K,N] (+D) ==============
// MODE 0: plain (optional D residual add)
// MODE 1: MoE gather — A rows gathered from token list, B expert-selected
// MODE 2: MoE scatter — A rows direct (hbuf), B expert-selected, C scattered
// BM=BN=128, BK=16, 4-stage cp.async pipeline, 256 threads (8 warps, 32x64 each).
template <int MODE>
__global__ void __launch_bounds__(256, 2) mmt_core(
    GB gb, int M, int N, int K) {
    extern __shared__ float smf[];
    __shared__ int spoff[NEXP + 1];
    __shared__ int scnt[NEXP];
    int z = blockIdx.z;
    const float* A = gb.A[z];
    const float* B = gb.B[z];
    const float* Dres = gb.D[z];
    float* C = gb.C[z];
    int tid = threadIdx.x, lane = tid & 31, wid = tid >> 5;
    int m0 = blockIdx.y * 128, n0 = blockIdx.x * 128;
    int e = 0;
    if (MODE != 0) {
        if (tid <= NEXP) spoff[tid] = g_poff[tid];
        if (tid < NEXP) scnt[tid] = g_cnt[tid];
        __syncthreads();
        if (m0 >= spoff[NEXP]) return;
        while (m0 >= spoff[e + 1]) e++;
        B += (size_t)e * K * N;
    }
    int wm = (wid & 3) * 32, wn = (wid >> 2) * 64;
    int arow = tid >> 1, ahalf = (tid & 1) * 8;
    int brow = tid >> 4, bcol = (tid & 15) * 8;
    const float* asrc;
    if (MODE == 1) {
        int grow = m0 + arow;
        int tok = ((grow - spoff[e]) < scnt[e]) ? (g_list[grow] >> 1) : 0;
        asrc = A + (size_t)tok * K + ahalf;
    } else {
        asrc = A + (size_t)(m0 + arow) * K + ahalf;
    }
    const float* bsrc = B + (size_t)brow * N + n0 + bcol;

    uint32_t smem_u = (uint32_t)__cvta_generic_to_shared(smf);
    uint32_t a_dst0 = smem_u + (arow * ASTR + ahalf) * 4;
    uint32_t b_dst0 = smem_u + (A_ST + brow * BSTR + bcol) * 4;

    float acc[2][8][4];
    #pragma unroll
    for (int mi = 0; mi < 2; mi++)
        #pragma unroll
        for (int nj = 0; nj < 8; nj++)
            #pragma unroll
            for (int q = 0; q < 4; q++) acc[mi][nj][q] = 0.f;

    int kiters = K >> 4;
    #pragma unroll
    for (int s = 0; s < NSTAGE - 1; s++) {
        int k0 = s * 16;
        uint32_t so = s * (STAGE_F * 4);
        cpa16(a_dst0 + so, asrc + k0);
        cpa16(a_dst0 + so + 16, asrc + k0 + 4);
        cpa16(b_dst0 + so, bsrc + (size_t)k0 * N);
        cpa16(b_dst0 + so + 16, bsrc + (size_t)k0 * N + 4);
        cpa_commit();
    }

    int r = lane >> 2, c = lane & 3;
    for (int it = 0; it < kiters; it++) {
        cpa_wait<NSTAGE - 2>();
        __syncthreads();
        int nk = it + NSTAGE - 1;
        if (nk < kiters) {
            int s = nk & (NSTAGE - 1);
            int k0 = nk * 16;
            uint32_t so = s * (STAGE_F * 4);
            cpa16(a_dst0 + so, asrc + k0);
            cpa16(a_dst0 + so + 16, asrc + k0 + 4);
            cpa16(b_dst0 + so, bsrc + (size_t)k0 * N);
            cpa16(b_dst0 + so + 16, bsrc + (size_t)k0 * N + 4);
        }
        cpa_commit();

        const float* Asb = smf + (it & (NSTAGE - 1)) * STAGE_F;
        const float* Bsb = Asb + A_ST;
        #pragma unroll
        for (int ks = 0; ks < 2; ks++) {
            int kk = ks * 8;
            unsigned af[2][4];
            #pragma unroll
            for (int mi = 0; mi < 2; mi++) {
                const float* ab = Asb + (wm + mi * 16 + r) * ASTR + kk + c;
                af[mi][0] = __float_as_uint(ab[0]);
                af[mi][1] = __float_as_uint(ab[8 * ASTR]);
                af[mi][2] = __float_as_uint(ab[4]);
                af[mi][3] = __float_as_uint(ab[8 * ASTR + 4]);
            }
            #pragma unroll
            for (int nj = 0; nj < 8; nj++) {
                const float* bb = Bsb + (kk + c) * BSTR + wn + nj * 8 + r;
                unsigned b0 = __float_as_uint(bb[0]);
                unsigned b1 = __float_as_uint(bb[4 * BSTR]);
                mma8(acc[0][nj], af[0], b0, b1);
                mma8(acc[1][nj], af[1], b0, b1);
            }
        }
    }
    #pragma unroll
    for (int mi = 0; mi < 2; mi++) {
        #pragma unroll
        for (int h = 0; h < 2; h++) {
            int m = m0 + wm + mi * 16 + r + h * 8;
            if (MODE == 2) {
                if ((m - spoff[e]) >= scnt[e]) continue;
                int enc = g_list[m];  // 2*token + slot
                float* crow = C + (size_t)enc * N + n0 + wn;
                #pragma unroll
                for (int nj = 0; nj < 8; nj++) {
                    float2 v = {acc[mi][nj][h * 2], acc[mi][nj][h * 2 + 1]};
                    *(float2*)(crow + nj * 8 + c * 2) = v;
                }
            } else {
                float* crow = C + (size_t)m * N + n0 + wn;
                const float* drow = Dres ? (Dres + (size_t)m * N + n0 + wn) : nullptr;
                #pragma unroll
                for (int nj = 0; nj < 8; nj++) {
                    float2 v = {acc[mi][nj][h * 2], acc[mi][nj][h * 2 + 1]};
                    if (MODE == 0 && drow) {
                        float2 d = *(const float2*)(drow + nj * 8 + c * 2);
                        v.x += d.x; v.y += d.y;
                    }
                    *(float2*)(crow + nj * 8 + c * 2) = v;
                }
            }
        }
    }
}

// ---------------- elementwise: g = silu(g) * u ----------------------------------
__global__ void silumul_kernel(float* __restrict__ g, const float* __restrict__ u,
                               int n4) {
    int i = blockIdx.x * blockDim.x + threadIdx.x;
    if (i >= n4) return;
    float4 gv = ((float4*)g)[i];
    float4 uv = ((const float4*)u)[i];
    gv.x = silu_f(gv.x) * uv.x;
    gv.y = silu_f(gv.y) * uv.y;
    gv.z = silu_f(gv.z) * uv.z;
    gv.w = silu_f(gv.w) * uv.w;
    ((float4*)g)[i] = gv;
}

// ---------------- rmsnorm -------------------------------------------------------
__global__ void rmsnorm_kernel(const float* __restrict__ x,
                               const float* __restrict__ w,
                               float* __restrict__ out) {
    int t = blockIdx.x;
    const float* xr = x + (size_t)t * HDIM;
    float ss = 0.f;
    for (int h = threadIdx.x; h < HDIM; h += blockDim.x) {
        float v = xr[h];
        ss += v * v;
    }
    __shared__ float red[32];
    #pragma unroll
    for (int o = 16; o; o >>= 1) ss += __shfl_xor_sync(0xffffffffu, ss, o);
    if ((threadIdx.x & 31) == 0) red[threadIdx.x >> 5] = ss;
    __syncthreads();
    if (threadIdx.x < 32) {
        float v = (threadIdx.x < (blockDim.x >> 5)) ? red[threadIdx.x] : 0.f;
        #pragma unroll
        for (int o = 16; o; o >>= 1) v += __shfl_xor_sync(0xffffffffu, v, o);
        if (threadIdx.x == 0) red[0] = v;
    }
    __syncthreads();
    float inv = 1.0f / (sqrtf(red[0] * (1.0f / HDIM)) + 1e-5f);
    float* orow = out + (size_t)t * HDIM;
    for (int h = threadIdx.x; h < HDIM; h += blockDim.x)
        orow[h] = xr[h] * inv * w[h];
}

// ---------------- RoPE + concat into qq/kk [T, NH, 64] --------------------------
__global__ void rope_concat_kernel() {
    int i = blockIdx.x * blockDim.x + threadIdx.x;  // over TT*NHEAD*HH
    if (i >= TT * NHEAD * HH) return;
    int d = i & 31;
    int h = (i >> 5) & 15;
    int t = i >> 9;
    int s = t & (SS - 1);
    int j = d & 15;
    float invf = expf(-((float)j / 16.0f) * 9.210340371976184f);  // ln(10000)
    float ang = (float)s * invf;
    float c = cosf(ang), sn = sinf(ang);
    int o = t * HDIM + h * HD + d;
    float kr = g_kropeb[i];
    float krot = (d < 16) ? -g_kropeb[i + 16] : g_kropeb[i - 16];
    g_kk[o] = g_khalf[i];
    g_kk[o + HH] = kr * c + krot * sn;
    float qr = g_qropeb[i];
    float qrot = (d < 16) ? -g_qropeb[i + 16] : g_qropeb[i - 16];
    g_qq[o] = g_qhalf[i];
    g_qq[o + HH] = qr * c + qrot * sn;
}

// ============ flash attention on TF32 tensor cores: causal, 64x64, d=64 =========
__global__ void __launch_bounds__(128, 2) flash_kernel() {
    extern __shared__ float sm[];
    float* Kst = sm;                 // [d][kcol]   64 x FD
    float* Vs  = sm + 64 * FD;       // [kcol][d]   64 x FD
    float* Ps  = sm + 2 * 64 * FD;   // [q][kcol]   64 x FD
    int qt = blockIdx.x, h = blockIdx.y, b = blockIdx.z;
    int tid = threadIdx.x, lane = tid & 31, wq = tid >> 5;
    int gr = lane >> 2, gc = lane & 3;

    unsigned aq[8][4];
    {
        const float* q0 = g_qq + ((size_t)(b * SS + qt * 64 + wq * 16 + gr)) * HDIM + h * HD;
        const float* q8 = q0 + 8 * HDIM;
        #pragma unroll
        for (int ks = 0; ks < 8; ks++) {
            int kk = ks * 8;
            aq[ks][0] = __float_as_uint(q0[kk + gc] * 0.125f);
            aq[ks][1] = __float_as_uint(q8[kk + gc] * 0.125f);
            aq[ks][2] = __float_as_uint(q0[kk + gc + 4] * 0.125f);
            aq[ks][3] = __float_as_uint(q8[kk + gc + 4] * 0.125f);
        }
    }
    float m_[2] = {-3.4e38f, -3.4e38f}, l_[2] = {0.f, 0.f};
    float o[8][4];
    #pragma unroll
    for (int nj = 0; nj < 8; nj++)
        #pragma unroll
        for (int q = 0; q < 4; q++) o[nj][q] = 0.f;

    for (int kt = 0; kt <= qt; kt++) {
        __syncthreads();
        {
            int r = tid >> 1;
            int c0 = (tid & 1) * 32;
            const float* ksrc = g_kk + ((size_t)(b * SS + kt * 64 + r)) * HDIM + h * HD + c0;
            const float* vsrc = g_v + ((size_t)(b * SS + kt * 64 + r)) * HDIM + h * HD + c0;
            #pragma unroll
            for (int u = 0; u < 8; u++) {
                float4 kv = *(const float4*)(ksrc + u * 4);
                Kst[(c0 + u * 4 + 0) * FD + r] = kv.x;
                Kst[(c0 + u * 4 + 1) * FD + r] = kv.y;
                Kst[(c0 + u * 4 + 2) * FD + r] = kv.z;
                Kst[(c0 + u * 4 + 3) * FD + r] = kv.w;
                *(float4*)&Vs[r * FD + c0 + u * 4] = *(const float4*)(vsrc + u * 4);
            }
        }
        __syncthreads();

        float s[8][4] = {};
        #pragma unroll
        for (int ks = 0; ks < 8; ks++) {
            int kk = ks * 8;
            #pragma unroll
            for (int nj = 0; nj < 8; nj++) {
                const float* bb = &Kst[(kk + gc) * FD + nj * 8 + gr];
                mma8(s[nj], aq[ks], __float_as_uint(bb[0]), __float_as_uint(bb[4 * FD]));
            }
        }
        if (kt == qt) {
            int row0 = wq * 16 + gr;
            #pragma unroll
            for (int nj = 0; nj < 8; nj++) {
                int col0 = nj * 8 + 2 * gc;
                if (col0 > row0) s[nj][0] = -3.4e38f;
                if (col0 + 1 > row0) s[nj][1] = -3.4e38f;
                if (col0 > row0 + 8) s[nj][2] = -3.4e38f;
                if (col0 + 1 > row0 + 8) s[nj][3] = -3.4e38f;
            }
        }
        #pragma unroll
        for (int q2 = 0; q2 < 2; q2++) {
            float mx = -3.4e38f;
            #pragma unroll
            for (int nj = 0; nj < 8; nj++)
                mx = fmaxf(mx, fmaxf(s[nj][q2 * 2], s[nj][q2 * 2 + 1]));
            mx = fmaxf(mx, __shfl_xor_sync(0xffffffffu, mx, 1));
            mx = fmaxf(mx, __shfl_xor_sync(0xffffffffu, mx, 2));
            float mnew = fmaxf(m_[q2], mx);
            float alpha = __expf(m_[q2] - mnew);
            float sum = 0.f;
            #pragma unroll
            for (int nj = 0; nj < 8; nj++) {
                float p0 = __expf(s[nj][q2 * 2] - mnew);
                float p1 = __expf(s[nj][q2 * 2 + 1] - mnew);
                s[nj][q2 * 2] = p0;
                s[nj][q2 * 2 + 1] = p1;
                sum += p0 + p1;
            }
            sum += __shfl_xor_sync(0xffffffffu, sum, 1);
            sum += __shfl_xor_sync(0xffffffffu, sum, 2);
            l_[q2] = l_[q2] * alpha + sum;
            m_[q2] = mnew;
            #pragma unroll
            for (int nj = 0; nj < 8; nj++) {
                o[nj][q2 * 2] *= alpha;
                o[nj][q2 * 2 + 1] *= alpha;
            }
        }
        {
            int r0 = wq * 16 + gr;
            #pragma unroll
            for (int nj = 0; nj < 8; nj++) {
                *(float2*)&Ps[r0 * FD + nj * 8 + 2 * gc] = make_float2(s[nj][0], s[nj][1]);
                *(float2*)&Ps[(r0 + 8) * FD + nj * 8 + 2 * gc] = make_float2(s[nj][2], s[nj][3]);
            }
        }
        __syncwarp();
        #pragma unroll
        for (int ks = 0; ks < 8; ks++) {
            int kk = ks * 8;
            int r0 = wq * 16 + gr;
            unsigned ap[4];
            ap[0] = __float_as_uint(Ps[r0 * FD + kk + gc]);
            ap[1] = __float_as_uint(Ps[(r0 + 8) * FD + kk + gc]);
            ap[2] = __float_as_uint(Ps[r0 * FD + kk + gc + 4]);
            ap[3] = __float_as_uint(Ps[(r0 + 8) * FD + kk + gc + 4]);
            #pragma unroll
            for (int nj = 0; nj < 8; nj++) {
                const float* bb = &Vs[(kk + gc) * FD + nj * 8 + gr];
                mma8(o[nj], ap, __float_as_uint(bb[0]), __float_as_uint(bb[4 * FD]));
            }
        }
        __syncwarp();
    }
    float inv0 = 1.0f / l_[0], inv1 = 1.0f / l_[1];
    int row0 = b * SS + qt * 64 + wq * 16 + gr;
    float* out0 = g_y + (size_t)row0 * HDIM + h * HD;
    float* out8 = out0 + 8 * HDIM;
    #pragma unroll
    for (int nj = 0; nj < 8; nj++) {
        *(float2*)&out0[nj * 8 + 2 * gc] = make_float2(o[nj][0] * inv0, o[nj][1] * inv0);
        *(float2*)&out8[nj * 8 + 2 * gc] = make_float2(o[nj][2] * inv1, o[nj][3] * inv1);
    }
}

// ---------------- router ---------------------------------------------------------
__global__ void zero_cnt_kernel() {
    if (threadIdx.x < NEXP) g_cnt[threadIdx.x] = 0;
}

__global__ void router_kernel(const float* __restrict__ Wr,
                              const float* __restrict__ bias) {
    int t = blockIdx.x * (blockDim.x >> 5) + (threadIdx.x >> 5);
    int lane = threadIdx.x & 31;
    if (t >= TT) return;
    const float* xr = g_xn2 + (size_t)t * HDIM;
    float acc[NEXP] = {};
    for (int h = lane; h < HDIM; h += 32) {
        float xv = xr[h];
        #pragma unroll
        for (int e = 0; e < NEXP; e++)
            acc[e] = fmaf(xv, Wr[h * NEXP + e], acc[e]);
    }
    #pragma unroll
    for (int e = 0; e < NEXP; e++)
        #pragma unroll
        for (int o = 16; o; o >>= 1)
            acc[e] += __shfl_xor_sync(0xffffffffu, acc[e], o);
    if (lane == 0) {
        float p[NEXP];
        #pragma unroll
        for (int e = 0; e < NEXP; e++)
            p[e] = 1.0f / (1.0f + expf(-(acc[e] + bias[e])));
        int i0 = 0;
        #pragma unroll
        for (int e = 1; e < NEXP; e++) if (p[e] > p[i0]) i0 = e;
        int i1 = (i0 == 0) ? 1 : 0;
        #pragma unroll
        for (int e = 0; e < NEXP; e++)
            if (e != i0 && p[e] > p[i1]) i1 = e;
        float ssum = p[i0] + p[i1];
        g_topidx[2 * t] = i0;
        g_topidx[2 * t + 1] = i1;
        g_topwt[2 * t] = p[i0] / ssum;
        g_topwt[2 * t + 1] = p[i1] / ssum;
        atomicAdd(&g_cnt[i0], 1);
        atomicAdd(&g_cnt[i1], 1);
    }
}

__global__ void prefix_kernel() {
    if (threadIdx.x == 0) {
        int off = 0;
        for (int e = 0; e < NEXP; e++) {
            g_poff[e] = off;
            off += (g_cnt[e] + 127) & ~127;   // pad segments to 128 rows
            g_fill[e] = 0;
        }
        g_poff[NEXP] = off;
    }
}

__global__ void scatter_kernel() {
    int t = blockIdx.x * blockDim.x + threadIdx.x;
    if (t >= TT) return;
    #pragma unroll
    for (int s = 0; s < 2; s++) {
        int e = g_topidx[2 * t + s];
        int pos = atomicAdd(&g_fill[e], 1);
        g_list[g_poff[e] + pos] = 2 * t + s;
    }
}

// ---------------- final combine: out = x1 + shared + w0*slot0 + w1*slot1 --------
__global__ void combine_kernel(float* __restrict__ out) {
    int i = blockIdx.x * blockDim.x + threadIdx.x;  // over TT*HDIM/4
    if (i >= TT * HDIM / 4) return;
    int c = i & (HDIM / 4 - 1);
    int t = i / (HDIM / 4);
    float w0 = g_topwt[2 * t], w1 = g_topwt[2 * t + 1];
    float4 a = ((const float4*)g_x1)[i];
    float4 sh = ((const float4*)g_sharedo)[i];
    float4 s0 = ((const float4*)g_slot)[(size_t)(2 * t) * (HDIM / 4) + c];
    float4 s1 = ((const float4*)g_slot)[(size_t)(2 * t + 1) * (HDIM / 4) + c];
    float4 r;
    r.x = a.x + sh.x + w0 * s0.x + w1 * s1.x;
    r.y = a.y + sh.y + w0 * s0.y + w1 * s1.y;
    r.z = a.z + sh.z + w0 * s0.z + w1 * s1.z;
    r.w = a.w + sh.w + w0 * s0.w + w1 * s1.w;
    ((float4*)out)[i] = r;
}

// ================================ host launcher =================================
static float* sym_f(const void* s) {
    void* p = nullptr;
    cudaGetSymbolAddress(&p, s);
    return (float*)p;
}

static GB mkgb(const float* a0, const float* b0, const float* d0, float* c0,
               const float* a1 = nullptr, const float* b1 = nullptr,
               const float* d1 = nullptr, float* c1 = nullptr,
               const float* a2 = nullptr, const float* b2 = nullptr,
               const float* d2 = nullptr, float* c2 = nullptr) {
    GB g;
    g.A[0] = a0; g.B[0] = b0; g.D[0] = d0; g.C[0] = c0;
    g.A[1] = a1; g.B[1] = b1; g.D[1] = d1; g.C[1] = c1;
    g.A[2] = a2; g.B[2] = b2; g.D[2] = d2; g.C[2] = c2;
    return g;
}

extern "C" void kernel_launch(void* const* d_in, const int* in_sizes, int n_in,
                              void* d_out, int out_size) {
    const float* x        = (const float*)d_in[0];
    const float* w_ln1    = (const float*)d_in[1];
    const float* w_ln2    = (const float*)d_in[2];
    const float* W_kvd    = (const float*)d_in[3];
    const float* W_qd     = (const float*)d_in[4];
    const float* W_ku     = (const float*)d_in[5];
    const float* W_qu     = (const float*)d_in[6];
    const float* W_vu     = (const float*)d_in[7];
    const float* W_ropeq  = (const float*)d_in[8];
    const float* W_ropek  = (const float*)d_in[9];
    const float* W_o      = (const float*)d_in[10];
    const float* Wg_s     = (const float*)d_in[11];
    const float* Wu_s     = (const float*)d_in[12];
    const float* Wd_s     = (const float*)d_in[13];
    const float* Wg_r     = (const float*)d_in[14];
    const float* Wu_r     = (const float*)d_in[15];
    const float* Wd_r     = (const float*)d_in[16];
    const float* W_router = (const float*)d_in[17];
    const float* r_bias   = (const float*)d_in[18];
    float* out = (float*)d_out;

    float* xn1    = sym_f(g_xn1);
    float* kvlat  = sym_f(g_kvlat);
    float* qlat   = sym_f(g_qlat);
    float* khalf  = sym_f(g_khalf);
    float* qhalf  = sym_f(g_qhalf);
    float* qropeb = sym_f(g_qropeb);
    float* kropeb = sym_f(g_kropeb);
    float* vbuf   = sym_f(g_v);
    float* ybuf   = sym_f(g_y);
    float* x1     = sym_f(g_x1);
    float* xn2    = sym_f(g_xn2);
    float* hmids  = sym_f(g_hmids);
    float* hmidu  = sym_f(g_hmidu);
    float* sharedo = sym_f(g_sharedo);
    float* hbuf   = sym_f(g_hbuf);
    float* hbufu  = sym_f(g_hbufu);
    float* slot   = sym_f(g_slot);

    cudaFuncSetAttribute(flash_kernel, cudaFuncAttributeMaxDynamicSharedMemorySize,
                         FLASH_SMEM_TC);
    cudaFuncSetAttribute(mmt_core<0>, cudaFuncAttributeMaxDynamicSharedMemorySize,
                         MMT_SMEM);
    cudaFuncSetAttribute(mmt_core<1>, cudaFuncAttributeMaxDynamicSharedMemorySize,
                         MMT_SMEM);
    cudaFuncSetAttribute(mmt_core<2>, cudaFuncAttributeMaxDynamicSharedMemorySize,
                         MMT_SMEM);

    // ---- MLA ----
    rmsnorm_kernel<<<TT, 256>>>(x, w_ln1, xn1);
    // batch: {kvlat = xn1@W_kvd, qlat = xn1@W_qd}  [TT,256] K=1024
    mmt_core<0><<<dim3(LAT / 128, TT / 128, 2), 256, MMT_SMEM>>>(
        mkgb(xn1, W_kvd, nullptr, kvlat, xn1, W_qd, nullptr, qlat), TT, LAT, HDIM);
    // ropek: [TT,512] K=1024
    mmt_core<0><<<dim3(512 / 128, TT / 128, 1), 256, MMT_SMEM>>>(
        mkgb(xn1, W_ropek, nullptr, kropeb), TT, 512, HDIM);
    // batch: {khalf = kvlat@W_ku, qhalf = qlat@W_qu, qropeb = qlat@W_ropeq} [TT,512] K=256
    mmt_core<0><<<dim3(512 / 128, TT / 128, 3), 256, MMT_SMEM>>>(
        mkgb(kvlat, W_ku, nullptr, khalf,
             qlat, W_qu, nullptr, qhalf,
             qlat, W_ropeq, nullptr, qropeb), TT, 512, LAT);
    // v = kvlat@W_vu  [TT,1024] K=256
    mmt_core<0><<<dim3(HDIM / 128, TT / 128, 1), 256, MMT_SMEM>>>(
        mkgb(kvlat, W_vu, nullptr, vbuf), TT, HDIM, LAT);
    {
        int n = TT * NHEAD * HH;
        rope_concat_kernel<<<(n + 255) / 256, 256>>>();
    }
    flash_kernel<<<dim3(SS / 64, NHEAD, BB), 128, FLASH_SMEM_TC>>>();
    // x1 = x + y @ W_o
    mmt_core<0><<<dim3(HDIM / 128, TT / 128, 1), 256, MMT_SMEM>>>(
        mkgb(ybuf, W_o, x, x1), TT, HDIM, HDIM);

    // ---- MoE ----
    rmsnorm_kernel<<<TT, 256>>>(x1, w_ln2, xn2);
    zero_cnt_kernel<<<1, 32>>>();
    router_kernel<<<TT / 4, 128>>>(W_router, r_bias);
    prefix_kernel<<<1, 32>>>();
    scatter_kernel<<<(TT + 255) / 256, 256>>>();
    // shared expert: batch {hmids = xn2@Wg_s, hmidu = xn2@Wu_s}
    mmt_core<0><<<dim3(IDIM / 128, TT / 128, 2), 256, MMT_SMEM>>>(
        mkgb(xn2, Wg_s, nullptr, hmids, xn2, Wu_s, nullptr, hmidu), TT, IDIM, HDIM);
    silumul_kernel<<<(TT * IDIM / 4 + 255) / 256, 256>>>(hmids, hmidu, TT * IDIM / 4);
    mmt_core<0><<<dim3(HDIM / 128, TT / 128, 1), 256, MMT_SMEM>>>(
        mkgb(hmids, Wd_s, nullptr, sharedo), TT, HDIM, IDIM);
    // routed experts: batch {hbuf = gather@Wg_r, hbufu = gather@Wu_r}
    mmt_core<1><<<dim3(IDIM / 128, HBUF_ROWS / 128, 2), 256, MMT_SMEM>>>(
        mkgb(xn2, Wg_r, nullptr, hbuf, xn2, Wu_r, nullptr, hbufu),
        HBUF_ROWS, IDIM, HDIM);
    silumul_kernel<<<(HBUF_ROWS * IDIM / 4 + 255) / 256, 256>>>(
        hbuf, hbufu, HBUF_ROWS * IDIM / 4);
    mmt_core<2><<<dim3(HDIM / 128, HBUF_ROWS / 128, 1), 256, MMT_SMEM>>>(
        mkgb(hbuf, Wd_r, nullptr, slot), HBUF_ROWS, HDIM, IDIM);
    // out = x1 + shared + weighted routed
    combine_kernel<<<(TT * HDIM / 4 + 255) / 256, 256>>>(out);
}